// round 11
// baseline (speedup 1.0000x reference)
#include <cuda_runtime.h>
#include <cuda_fp16.h>
#include <cstdint>
#include <cstddef>

// ---------------- problem dimensions ----------------
static constexpr int N_NODES = 16384;
static constexpr int NE      = 131072;
static constexpr int NE_RO   = 32768;
static constexpr int D       = 1024;
static constexpr int DL      = 300;
static constexpr int DS      = 16;
static constexpr int NC      = 117;

// ---------------- fp32 scratch (readout precursors) ----------------
static constexpr size_t SZ_NC   = (size_t)N_NODES * NC;
static constexpr size_t SZ_SPRO = (size_t)NE_RO * NC;
static constexpr size_t OFF_RD   = 0;
static constexpr size_t OFF_RS   = OFF_RD + SZ_NC;
static constexpr size_t OFF_SPRO = OFF_RS + SZ_NC;
static constexpr size_t TOTAL_F32 = OFF_SPRO + SZ_SPRO;
__device__ float g_scratch[TOTAL_F32];

// ---------------- fp16 scratch ----------------
static constexpr size_t HOFF_FA   = 0;                               // [N][2048] = [feat|AGG]
static constexpr size_t HSZ_FA    = (size_t)N_NODES * 2048;
static constexpr size_t HOFF_WA   = HOFF_FA + HSZ_FA;                // [N][608]  = [w2v|AGGL|pad]
static constexpr size_t HSZ_WA    = (size_t)N_NODES * 608;
static constexpr size_t HOFF_NFA  = HOFF_WA + HSZ_WA;                // [N][1328] = [NF|NFL|pad]
static constexpr size_t HSZ_NFA   = (size_t)N_NODES * 1328;
static constexpr size_t HOFF_P1   = HOFF_NFA + HSZ_NFA;
static constexpr size_t HSZ_P     = (size_t)N_NODES * 1024;
static constexpr size_t HOFF_P2   = HOFF_P1 + HSZ_P;
static constexpr size_t HOFF_Q1   = HOFF_P2 + HSZ_P;
static constexpr size_t HSZ_Q     = (size_t)N_NODES * 304;
static constexpr size_t HOFF_Q2   = HOFF_Q1 + HSZ_Q;
static constexpr size_t HOFF_SP   = HOFF_Q2 + HSZ_Q;
static constexpr size_t HSZ_SP    = (size_t)NE * 1024;
static constexpr size_t HOFF_SFH  = HOFF_SP + HSZ_SP;
static constexpr size_t HSZ_SFH   = (size_t)NE * 16;
static constexpr size_t HOFF_SFRO = HOFF_SFH + HSZ_SFH;
static constexpr size_t HSZ_SFRO  = (size_t)NE_RO * 16;
// fp16 transposed weights  W^T [Nn][Kpad]
static constexpr size_t HOFF_WE1  = HOFF_SFRO + HSZ_SFRO;   // [1024][1024]
static constexpr size_t HOFF_WE2  = HOFF_WE1 + 1024 * 1024;
static constexpr size_t HOFF_WS   = HOFF_WE2 + 1024 * 1024; // [1024][16]
static constexpr size_t HOFF_WEL1 = HOFF_WS  + 1024 * 16;   // [300][304]
static constexpr size_t HOFF_WEL2 = HOFF_WEL1 + 300 * 304;
static constexpr size_t HOFF_WNU  = HOFF_WEL2 + 300 * 304;  // [1024][2048]
static constexpr size_t HOFF_WNUL = HOFF_WNU + 1024 * 2048; // [300][608]
static constexpr size_t HOFF_WRD  = HOFF_WNUL + 300 * 608;  // [117][1328]
static constexpr size_t HOFF_WRS  = HOFF_WRD + 117 * 1328;  // [117][1328]
static constexpr size_t HOFF_WSP  = HOFF_WRS + 117 * 1328;  // [117][16]
static constexpr size_t TOTAL_H   = HOFF_WSP + 117 * 16;
__device__ __half g_hscratch[TOTAL_H];

// int scratch
static constexpr size_t IOFF_DEG  = 0;
static constexpr size_t IOFF_RS_  = IOFF_DEG + N_NODES;
static constexpr size_t IOFF_CUR  = IOFF_RS_ + N_NODES + 1;
static constexpr size_t IOFF_PERM = IOFF_CUR + N_NODES;
__device__ int g_iscratch[IOFF_PERM + NE];

// ---------------- CSR build kernels ----------------
__global__ void zero_int_kernel(int* __restrict__ p, int n) {
    int i = blockIdx.x * blockDim.x + threadIdx.x;
    if (i < n) p[i] = 0;
}
__global__ void hist_kernel(const int* __restrict__ edst, int* __restrict__ deg) {
    int e = blockIdx.x * blockDim.x + threadIdx.x;
    if (e < NE) atomicAdd(&deg[edst[e]], 1);
}
__global__ __launch_bounds__(512)
void scan_kernel(const int* __restrict__ deg, int* __restrict__ row_start,
                 int* __restrict__ cursor) {
    __shared__ int part[512];
    int tid = threadIdx.x;
    int base = tid * 32;
    int loc[32];
    int s = 0;
#pragma unroll
    for (int j = 0; j < 32; j++) { loc[j] = s; s += deg[base + j]; }
    part[tid] = s;
    __syncthreads();
    for (int off = 1; off < 512; off <<= 1) {
        int v = (tid >= off) ? part[tid - off] : 0;
        __syncthreads();
        part[tid] += v;
        __syncthreads();
    }
    int pre = (tid > 0) ? part[tid - 1] : 0;
#pragma unroll
    for (int j = 0; j < 32; j++) {
        int v = pre + loc[j];
        row_start[base + j] = v;
        cursor[base + j] = v;
    }
    if (tid == 511) row_start[N_NODES] = part[511];
}
__global__ void scatter_kernel(const int* __restrict__ edst, int* __restrict__ cursor,
                               int* __restrict__ perm) {
    int e = blockIdx.x * blockDim.x + threadIdx.x;
    if (e < NE) {
        int pos = atomicAdd(&cursor[edst[e]], 1);
        perm[pos] = e;
    }
}

// ---------------- conversion kernels ----------------
__global__ __launch_bounds__(256)
void conv_node_kernel(const float* __restrict__ feat, const float* __restrict__ w2v,
                      __half* __restrict__ FA, __half* __restrict__ WA,
                      __half* __restrict__ NFA)
{
    int n = blockIdx.x, tid = threadIdx.x;
    float4 f = *(const float4*)(feat + (size_t)n * 1024 + tid * 4);
    __half2 h0 = __floats2half2_rn(f.x, f.y);
    __half2 h1 = __floats2half2_rn(f.z, f.w);
    uint2 u; u.x = *(uint32_t*)&h0; u.y = *(uint32_t*)&h1;
    *(uint2*)(FA + (size_t)n * 2048 + tid * 4) = u;
    if (tid < 75) {
        float4 w = *(const float4*)(w2v + (size_t)n * 300 + tid * 4);
        __half2 g0 = __floats2half2_rn(w.x, w.y);
        __half2 g1 = __floats2half2_rn(w.z, w.w);
        uint2 v; v.x = *(uint32_t*)&g0; v.y = *(uint32_t*)&g1;
        *(uint2*)(WA + (size_t)n * 608 + tid * 4) = v;
    } else if (tid == 75) {
        uint2 z = make_uint2(0, 0);
        *(uint2*)(WA + (size_t)n * 608 + 600) = z;
        *(uint2*)(WA + (size_t)n * 608 + 604) = z;
    } else if (tid == 76) {
        uint2 z = make_uint2(0, 0);
        *(uint2*)(NFA + (size_t)n * 1328 + 1324) = z;
    }
}

__global__ void conv_sf_kernel(const float* __restrict__ s_f, const float* __restrict__ s_f_ro,
                               __half* __restrict__ sfh, __half* __restrict__ sfroh)
{
    size_t i = (size_t)blockIdx.x * blockDim.x + threadIdx.x;
    size_t n1 = (size_t)NE * 8;
    size_t tot = n1 + (size_t)NE_RO * 8;
    if (i >= tot) return;
    if (i < n1) {
        float2 f = *(const float2*)(s_f + i * 2);
        __half2 h = __floats2half2_rn(f.x, f.y);
        *(uint32_t*)(sfh + i * 2) = *(uint32_t*)&h;
    } else {
        size_t j = i - n1;
        float2 f = *(const float2*)(s_f_ro + j * 2);
        __half2 h = __floats2half2_rn(f.x, f.y);
        *(uint32_t*)(sfroh + j * 2) = *(uint32_t*)&h;
    }
}

// ---------------- weight transpose+convert: dst[n][k] = f16(src[k][n]) ----------------
// ldd = destination row STRIDE; kmax = number of k-columns written (zero-padded from K..kmax).
struct TJob { const float* src; int ldsrc; int K; int Nn; __half* dst; int ldd; int kmax; };
struct TJobs { TJob j[11]; };

__global__ __launch_bounds__(256)
void wtrans_kernel(TJobs J)
{
    TJob jb = J.j[blockIdx.z];
    int k0 = blockIdx.x * 32, n0 = blockIdx.y * 32;
    if (k0 >= jb.kmax || n0 >= jb.Nn) return;
    __shared__ float s[32][33];
    int tx = threadIdx.x & 31, ty = threadIdx.x >> 5;
#pragma unroll
    for (int r = ty; r < 32; r += 8) {
        int k = k0 + r, n = n0 + tx;
        s[r][tx] = (k < jb.K && n < jb.Nn) ? jb.src[(size_t)k * jb.ldsrc + n] : 0.f;
    }
    __syncthreads();
#pragma unroll
    for (int r = ty; r < 32; r += 8) {
        int n = n0 + r, k = k0 + tx;
        if (n < jb.Nn && k < jb.kmax)
            jb.dst[(size_t)n * jb.ldd + k] = __float2half(s[tx][r]);
    }
}

// ---------------- mma + cp.async helpers ----------------
__device__ __forceinline__ void mma_f16(float* c, const uint32_t* a, const uint32_t* b) {
    asm volatile("mma.sync.aligned.m16n8k16.row.col.f32.f16.f16.f32 "
        "{%0,%1,%2,%3}, {%4,%5,%6,%7}, {%8,%9}, {%0,%1,%2,%3};"
        : "+f"(c[0]), "+f"(c[1]), "+f"(c[2]), "+f"(c[3])
        : "r"(a[0]), "r"(a[1]), "r"(a[2]), "r"(a[3]), "r"(b[0]), "r"(b[1]));
}
__device__ __forceinline__ uint32_t smem_u32(const void* p) {
    uint32_t a;
    asm("{ .reg .u64 t; cvta.to.shared.u64 t, %1; cvt.u32.u64 %0, t; }" : "=r"(a) : "l"(p));
    return a;
}
__device__ __forceinline__ void cp_async16(uint32_t dst, const void* src, int src_bytes) {
    asm volatile("cp.async.cg.shared.global [%0], [%1], 16, %2;"
                 :: "r"(dst), "l"(src), "r"(src_bytes) : "memory");
}
#define CP_COMMIT() asm volatile("cp.async.commit_group;" ::: "memory")
#define CP_WAIT(N)  asm volatile("cp.async.wait_group %0;" :: "n"(N) : "memory")

// ---------------- all-fp16 GEMM, cp.async 4-stage pipeline ----------------
// C = act(A @ Bt^T + bias); A fp16 [M][lda], Bt fp16 [Nn][ldb] zero-padded K..ldb.
struct GArgs {
    const __half* A; int lda; int K;
    const __half* Bt; int ldb;
    void* C; int ldc;
    const float* bias;
    int M; int Nn; int doRelu; int outHalf;
};
struct GArgs4 { GArgs g[4]; };

static constexpr int PAD_H        = 40;
static constexpr int TILE_BYTES_1 = 128 * PAD_H * 2;     // 10240
static constexpr int STG_BYTES    = 2 * TILE_BYTES_1;    // 20480
static constexpr int STAGES       = 4;
static constexpr int GM_SMEM      = STAGES * STG_BYTES;  // 81920

__global__ __launch_bounds__(256)
void gemm_h(GArgs4 P)
{
    extern __shared__ char smc[];
    GArgs ga = P.g[blockIdx.z];

    const int m0 = blockIdx.y * 128;
    const int n0 = blockIdx.x * 128;
    if (m0 >= ga.M || n0 >= ga.Nn) return;

    const int tid  = threadIdx.x;
    const int wid  = tid >> 5;
    const int lane = tid & 31;
    const int g    = lane >> 2;
    const int t    = lane & 3;
    const int K    = ga.K;
    const int nT   = (K + 31) / 32;
    const int wm   = wid & 3;
    const int wn   = wid >> 2;

    const uint32_t smb = smem_u32(smc);

    float acc[2][8][4];
#pragma unroll
    for (int i = 0; i < 2; i++)
#pragma unroll
        for (int j = 0; j < 8; j++)
#pragma unroll
            for (int k = 0; k < 4; k++) acc[i][j][k] = 0.f;

    auto issue_load = [&](int tt, int buf) {
        if (tt < nT) {
            const int k0 = tt * 32;
            uint32_t Ab = smb + (uint32_t)buf * STG_BYTES;
            uint32_t Bb = Ab + TILE_BYTES_1;
#pragma unroll
            for (int i = 0; i < 2; i++) {
                int idx = i * 256 + tid;
                int row = idx >> 2, c8 = idx & 3;
                int kb = k0 + c8 * 8;
                const __half* src = ga.A;
                int sz = 0;
                if (kb < K) { src = ga.A + (size_t)(m0 + row) * ga.lda + kb; sz = 16; }
                cp_async16(Ab + (uint32_t)(row * (PAD_H * 2) + c8 * 16), src, sz);
            }
#pragma unroll
            for (int i = 0; i < 2; i++) {
                int idx = i * 256 + tid;
                int row = idx >> 2, c8 = idx & 3;
                int kb = k0 + c8 * 8;
                const __half* src = ga.Bt;
                int sz = 0;
                if (kb < ga.ldb && (n0 + row) < ga.Nn) {
                    src = ga.Bt + (size_t)(n0 + row) * ga.ldb + kb; sz = 16;
                }
                cp_async16(Bb + (uint32_t)(row * (PAD_H * 2) + c8 * 16), src, sz);
            }
        }
        CP_COMMIT();
    };

    auto compute = [&](int buf) {
        const __half* As = (const __half*)(smc + buf * STG_BYTES) + (wm * 32) * PAD_H;
        const __half* Bs = (const __half*)(smc + buf * STG_BYTES + TILE_BYTES_1) + (wn * 64) * PAD_H;
#pragma unroll
        for (int ks = 0; ks < 2; ks++) {
            uint32_t ah[2][4];
#pragma unroll
            for (int mb = 0; mb < 2; mb++) {
#pragma unroll
                for (int r = 0; r < 4; r++) {
                    int rowq = mb * 16 + g + (r & 1) * 8;
                    int kq   = ks * 16 + t * 2 + (r >> 1) * 8;
                    ah[mb][r] = *(const uint32_t*)(As + rowq * PAD_H + kq);
                }
            }
            uint32_t bh[8][2];
#pragma unroll
            for (int nb = 0; nb < 8; nb++) {
#pragma unroll
                for (int r = 0; r < 2; r++) {
                    int kq = ks * 16 + t * 2 + r * 8;
                    bh[nb][r] = *(const uint32_t*)(Bs + (nb * 8 + g) * PAD_H + kq);
                }
            }
#pragma unroll
            for (int mb = 0; mb < 2; mb++) {
#pragma unroll
                for (int nb = 0; nb < 8; nb++) {
                    mma_f16(acc[mb][nb], ah[mb], bh[nb]);
                }
            }
        }
    };

#pragma unroll
    for (int s = 0; s < STAGES - 1; s++) issue_load(s, s);

    for (int tt = 0; tt < nT; tt++) {
        issue_load(tt + STAGES - 1, (tt + STAGES - 1) % STAGES);
        CP_WAIT(STAGES - 1);
        __syncthreads();
        compute(tt % STAGES);
        __syncthreads();
    }

    // ---- epilogue ----
#pragma unroll
    for (int mb = 0; mb < 2; mb++) {
#pragma unroll
        for (int nb = 0; nb < 8; nb++) {
            int n = n0 + wn * 64 + nb * 8 + t * 2;
            float bv0 = 0.f, bv1 = 0.f;
            if (ga.bias) {
                if (n     < ga.Nn) bv0 = ga.bias[n];
                if (n + 1 < ga.Nn) bv1 = ga.bias[n + 1];
            }
#pragma unroll
            for (int h = 0; h < 2; h++) {
                int m = m0 + wm * 32 + mb * 16 + g + h * 8;
                float v0 = acc[mb][nb][h * 2 + 0] + bv0;
                float v1 = acc[mb][nb][h * 2 + 1] + bv1;
                if (ga.doRelu) { v0 = fmaxf(v0, 0.f); v1 = fmaxf(v1, 0.f); }
                if (ga.outHalf) {
                    if (n < ga.Nn) {
                        __half2 hv = __floats2half2_rn(v0, v1);
                        *(uint32_t*)((__half*)ga.C + (size_t)m * ga.ldc + n) = *(uint32_t*)&hv;
                    }
                } else {
                    float* cp = (float*)ga.C + (size_t)m * ga.ldc + n;
                    if (n     < ga.Nn) cp[0] = v0;
                    if (n + 1 < ga.Nn) cp[1] = v1;
                }
            }
        }
    }
}

// ---------------- appearance aggregation (CSR gather, fp16 data) ----------------
__global__ __launch_bounds__(256)
void agg_app_kernel(const __half* __restrict__ P1h, const __half* __restrict__ P2h,
                    const __half* __restrict__ SPh, const float* __restrict__ b_e,
                    const int* __restrict__ esrc, const int* __restrict__ perm,
                    const int* __restrict__ row_start, __half* __restrict__ FA)
{
    const int n = blockIdx.x;
    const int tid = threadIdx.x;
    const int start = row_start[n];
    const int nb = row_start[n + 1] - start;

    uint2 p2 = *(const uint2*)(P2h + (size_t)n * 1024 + tid * 4);
    float2 b0 = __half22float2(*(__half2*)&p2.x);
    float2 b1 = __half22float2(*(__half2*)&p2.y);
    float4 be = ((const float4*)b_e)[tid];
    float bx = b0.x + be.x, by = b0.y + be.y, bz = b1.x + be.z, bw = b1.y + be.w;

    float4 acc = make_float4(0.f, 0.f, 0.f, 0.f);
#pragma unroll 2
    for (int i = 0; i < nb; i++) {
        int e = __ldg(&perm[start + i]);
        int s = __ldg(&esrc[e]);
        uint2 a = *(const uint2*)(P1h + (size_t)s * 1024 + tid * 4);
        uint2 c = *(const uint2*)(SPh + (size_t)e * 1024 + tid * 4);
        float2 a0 = __half22float2(*(__half2*)&a.x);
        float2 a1 = __half22float2(*(__half2*)&a.y);
        float2 c0 = __half22float2(*(__half2*)&c.x);
        float2 c1 = __half22float2(*(__half2*)&c.y);
        acc.x += fmaxf(a0.x + c0.x + bx, 0.f);
        acc.y += fmaxf(a0.y + c0.y + by, 0.f);
        acc.z += fmaxf(a1.x + c1.x + bz, 0.f);
        acc.w += fmaxf(a1.y + c1.y + bw, 0.f);
    }
    float inv = 1.0f / (float)max(nb, 1);
    __half2 o0 = __floats2half2_rn(acc.x * inv, acc.y * inv);
    __half2 o1 = __floats2half2_rn(acc.z * inv, acc.w * inv);
    uint2 o; o.x = *(uint32_t*)&o0; o.y = *(uint32_t*)&o1;
    *(uint2*)(FA + (size_t)n * 2048 + 1024 + tid * 4) = o;
}

// ---------------- language aggregation (CSR gather, fp16 data) ----------------
__global__ __launch_bounds__(96)
void agg_lang_kernel(const __half* __restrict__ Q1h, const __half* __restrict__ Q2h,
                     const float* __restrict__ b_el,
                     const int* __restrict__ esrc, const int* __restrict__ perm,
                     const int* __restrict__ row_start, __half* __restrict__ WA)
{
    const int n = blockIdx.x;
    const int c4 = threadIdx.x;
    if (c4 >= DL / 4) return;
    const int start = row_start[n];
    const int nb = row_start[n + 1] - start;

    uint2 q2 = *(const uint2*)(Q2h + (size_t)n * 304 + c4 * 4);
    float2 b0 = __half22float2(*(__half2*)&q2.x);
    float2 b1 = __half22float2(*(__half2*)&q2.y);
    float4 be = ((const float4*)b_el)[c4];
    float bx = b0.x + be.x, by = b0.y + be.y, bz = b1.x + be.z, bw = b1.y + be.w;

    float4 acc = make_float4(0.f, 0.f, 0.f, 0.f);
#pragma unroll 2
    for (int i = 0; i < nb; i++) {
        int e = __ldg(&perm[start + i]);
        int s = __ldg(&esrc[e]);
        uint2 a = *(const uint2*)(Q1h + (size_t)s * 304 + c4 * 4);
        float2 a0 = __half22float2(*(__half2*)&a.x);
        float2 a1 = __half22float2(*(__half2*)&a.y);
        acc.x += fmaxf(a0.x + bx, 0.f);
        acc.y += fmaxf(a0.y + by, 0.f);
        acc.z += fmaxf(a1.x + bz, 0.f);
        acc.w += fmaxf(a1.y + bw, 0.f);
    }
    float inv = 1.0f / (float)max(nb, 1);
    __half2 o0 = __floats2half2_rn(acc.x * inv, acc.y * inv);
    __half2 o1 = __floats2half2_rn(acc.z * inv, acc.w * inv);
    uint2 o; o.x = *(uint32_t*)&o0; o.y = *(uint32_t*)&o1;
    *(uint2*)(WA + (size_t)n * 608 + 300 + c4 * 4) = o;
}

// ---------------- readout ----------------
__global__ __launch_bounds__(128)
void readout_kernel(const float* __restrict__ Rd, const float* __restrict__ Rs,
                    const float* __restrict__ SPro,
                    const int* __restrict__ rsrc, const int* __restrict__ rdst,
                    float* __restrict__ pred)
{
    int e = blockIdx.x;
    int c = threadIdx.x;
    if (c >= NC) return;
    int s = rsrc[e];
    int d = rdst[e];
    pred[(size_t)e * NC + c] = Rd[(size_t)d * NC + c] + Rs[(size_t)s * NC + c]
                             + SPro[(size_t)e * NC + c];
}

// ---------------- host launcher ----------------
extern "C" void kernel_launch(void* const* d_in, const int* in_sizes, int n_in,
                              void* d_out, int out_size)
{
    const float* feat   = (const float*)d_in[0];
    const float* w2v    = (const float*)d_in[1];
    const float* s_f    = (const float*)d_in[2];
    const float* s_f_ro = (const float*)d_in[3];
    const float* W_e    = (const float*)d_in[4];
    const float* b_e    = (const float*)d_in[5];
    const float* W_el   = (const float*)d_in[6];
    const float* b_el   = (const float*)d_in[7];
    const float* W_nu   = (const float*)d_in[8];
    const float* b_nu   = (const float*)d_in[9];
    const float* W_nul  = (const float*)d_in[10];
    const float* b_nul  = (const float*)d_in[11];
    const float* W_p    = (const float*)d_in[12];
    const float* b_p    = (const float*)d_in[13];
    const int* esrc = (const int*)d_in[14];
    const int* edst = (const int*)d_in[15];
    const int* rsrc = (const int*)d_in[16];
    const int* rdst = (const int*)d_in[17];
    float* pred = (float*)d_out;

    float* sc = nullptr;
    cudaGetSymbolAddress((void**)&sc, g_scratch);
    __half* hs = nullptr;
    cudaGetSymbolAddress((void**)&hs, g_hscratch);
    int* isc = nullptr;
    cudaGetSymbolAddress((void**)&isc, g_iscratch);

    float* RD   = sc + OFF_RD;
    float* RS   = sc + OFF_RS;
    float* SPRO = sc + OFF_SPRO;

    __half* FA    = hs + HOFF_FA;
    __half* WA    = hs + HOFF_WA;
    __half* NFA   = hs + HOFF_NFA;
    __half* P1h   = hs + HOFF_P1;
    __half* P2h   = hs + HOFF_P2;
    __half* Q1h   = hs + HOFF_Q1;
    __half* Q2h   = hs + HOFF_Q2;
    __half* SPh   = hs + HOFF_SP;
    __half* sfh   = hs + HOFF_SFH;
    __half* sfroh = hs + HOFF_SFRO;
    __half* WE1   = hs + HOFF_WE1;
    __half* WE2   = hs + HOFF_WE2;
    __half* WSs   = hs + HOFF_WS;
    __half* WEL1  = hs + HOFF_WEL1;
    __half* WEL2  = hs + HOFF_WEL2;
    __half* WNU   = hs + HOFF_WNU;
    __half* WNUL  = hs + HOFF_WNUL;
    __half* WRD   = hs + HOFF_WRD;
    __half* WRS   = hs + HOFF_WRS;
    __half* WSP   = hs + HOFF_WSP;

    int* deg  = isc + IOFF_DEG;
    int* rows = isc + IOFF_RS_;
    int* cur  = isc + IOFF_CUR;
    int* perm = isc + IOFF_PERM;

    cudaFuncSetAttribute(gemm_h, cudaFuncAttributeMaxDynamicSharedMemorySize, GM_SMEM);

    // ---- conversions ----
    conv_node_kernel<<<N_NODES, 256>>>(feat, w2v, FA, WA, NFA);
    {
        size_t pairs = ((size_t)NE + NE_RO) * 8;
        conv_sf_kernel<<<(unsigned)((pairs + 255) / 256), 256>>>(s_f, s_f_ro, sfh, sfroh);
    }
    // ---- weight transpose + convert (single launch; ldd = stride, kmax = write bound) ----
    {
        TJobs J;
        J.j[0]  = {W_e,                       D,  1024, 1024, WE1,  1024, 1024};
        J.j[1]  = {W_e + (size_t)D * D,       D,  1024, 1024, WE2,  1024, 1024};
        J.j[2]  = {W_e + (size_t)(2 * D) * D, D,  16,   1024, WSs,  16,   16};
        J.j[3]  = {W_el,                      DL, 300,  300,  WEL1, 304,  304};
        J.j[4]  = {W_el + (size_t)DL * DL,    DL, 300,  300,  WEL2, 304,  304};
        J.j[5]  = {W_nu,                      D,  2048, 1024, WNU,  2048, 2048};
        J.j[6]  = {W_nul,                     DL, 600,  300,  WNUL, 608,  608};
        J.j[7]  = {W_p,                       NC, 1324, NC,   WRD,  1328, 1328};
        J.j[8]  = {W_p + (size_t)(D + DL + DS + DL) * NC, NC, 1024, NC, WRS,        1328, 1024};
        J.j[9]  = {W_p + (size_t)(D + DL + DS) * NC,      NC, 300,  NC, WRS + 1024, 1328, 304};
        J.j[10] = {W_p + (size_t)(D + DL) * NC,           NC, 16,   NC, WSP,        16,   16};
        wtrans_kernel<<<dim3(64, 32, 11), 256>>>(J);
    }

    // ---- CSR build (by dst) ----
    zero_int_kernel<<<(N_NODES + 255) / 256, 256>>>(deg, N_NODES);
    hist_kernel<<<NE / 256, 256>>>(edst, deg);
    scan_kernel<<<1, 512>>>(deg, rows, cur);
    scatter_kernel<<<NE / 256, 256>>>(edst, cur, perm);

    dim3 blk(256);

    // ---- SP[e] = s_f @ Ws -> fp16 [NE,1024] ----
    {
        GArgs a{sfh, 16, 16, WSs, 16, SPh, 1024, nullptr, NE, 1024, 0, 1};
        GArgs4 P{{a, a, a, a}};
        gemm_h<<<dim3(8, NE / 128, 1), blk, GM_SMEM>>>(P);
    }
    // ---- P1, P2, Q1, Q2 merged ----
    {
        GArgs p1{FA, 2048, 1024, WE1, 1024, P1h, 1024, nullptr, N_NODES, 1024, 0, 1};
        GArgs p2{FA, 2048, 1024, WE2, 1024, P2h, 1024, nullptr, N_NODES, 1024, 0, 1};
        GArgs q1{WA, 608, 300, WEL1, 304, Q1h, 304, nullptr, N_NODES, 300, 0, 1};
        GArgs q2{WA, 608, 300, WEL2, 304, Q2h, 304, nullptr, N_NODES, 300, 0, 1};
        GArgs4 P{{p1, p2, q1, q2}};
        gemm_h<<<dim3(8, 128, 4), blk, GM_SMEM>>>(P);
    }
    // ---- aggregation (gather, no atomics) ----
    agg_app_kernel<<<N_NODES, 256>>>(P1h, P2h, SPh, b_e, esrc, perm, rows, FA);
    agg_lang_kernel<<<N_NODES, 96>>>(Q1h, Q2h, b_el, esrc, perm, rows, WA);

    // ---- node updates merged ----
    {
        GArgs nf {FA, 2048, 2048, WNU, 2048, NFA, 1328, b_nu, N_NODES, 1024, 1, 1};
        GArgs nfl{WA, 608, 600, WNUL, 608, NFA + 1024, 1328, b_nul, N_NODES, 300, 1, 1};
        GArgs4 P{{nf, nfl, nf, nfl}};
        gemm_h<<<dim3(8, 128, 2), blk, GM_SMEM>>>(P);
    }
    // ---- RD, RS, SPro merged ----
    {
        GArgs rd{NFA, 1328, 1324, WRD, 1328, RD, NC, nullptr, N_NODES, NC, 0, 0};
        GArgs rs{NFA, 1328, 1324, WRS, 1328, RS, NC, nullptr, N_NODES, NC, 0, 0};
        GArgs sp{sfroh, 16, 16, WSP, 16, SPRO, NC, b_p, NE_RO, NC, 0, 0};
        GArgs4 P{{rd, rs, sp, sp}};
        gemm_h<<<dim3(1, 256, 3), blk, GM_SMEM>>>(P);
    }

    // ---- final edge readout ----
    readout_kernel<<<NE_RO, 128>>>(RD, RS, SPRO, rsrc, rdst, pred);
}

// round 12
// speedup vs baseline: 1.0787x; 1.0787x over previous
#include <cuda_runtime.h>
#include <cuda_fp16.h>
#include <cstdint>
#include <cstddef>

// ---------------- problem dimensions ----------------
static constexpr int N_NODES = 16384;
static constexpr int NE      = 131072;
static constexpr int NE_RO   = 32768;
static constexpr int D       = 1024;
static constexpr int DL      = 300;
static constexpr int DS      = 16;
static constexpr int NC      = 117;

// ---------------- fp32 scratch (readout precursors) ----------------
static constexpr size_t SZ_NC   = (size_t)N_NODES * NC;
static constexpr size_t SZ_SPRO = (size_t)NE_RO * NC;
static constexpr size_t OFF_RD   = 0;
static constexpr size_t OFF_RS   = OFF_RD + SZ_NC;
static constexpr size_t OFF_SPRO = OFF_RS + SZ_NC;
static constexpr size_t TOTAL_F32 = OFF_SPRO + SZ_SPRO;
__device__ float g_scratch[TOTAL_F32];

// ---------------- fp16 scratch ----------------
static constexpr size_t HOFF_FA   = 0;                               // [N][2048] = [feat|AGG]
static constexpr size_t HSZ_FA    = (size_t)N_NODES * 2048;
static constexpr size_t HOFF_WA   = HOFF_FA + HSZ_FA;                // [N][608]  = [w2v|AGGL|pad]
static constexpr size_t HSZ_WA    = (size_t)N_NODES * 608;
static constexpr size_t HOFF_NFA  = HOFF_WA + HSZ_WA;                // [N][1328] = [NF|NFL|pad]
static constexpr size_t HSZ_NFA   = (size_t)N_NODES * 1328;
static constexpr size_t HOFF_P1   = HOFF_NFA + HSZ_NFA;
static constexpr size_t HSZ_P     = (size_t)N_NODES * 1024;
static constexpr size_t HOFF_P2   = HOFF_P1 + HSZ_P;
static constexpr size_t HOFF_Q1   = HOFF_P2 + HSZ_P;
static constexpr size_t HSZ_Q     = (size_t)N_NODES * 304;
static constexpr size_t HOFF_Q2   = HOFF_Q1 + HSZ_Q;
static constexpr size_t HOFF_SFRO = HOFF_Q2 + HSZ_Q;
static constexpr size_t HSZ_SFRO  = (size_t)NE_RO * 16;
static constexpr size_t TOTAL_H   = HOFF_SFRO + HSZ_SFRO;
__device__ __half g_hscratch[TOTAL_H];

// int scratch
static constexpr size_t IOFF_DEG  = 0;
static constexpr size_t IOFF_RS_  = IOFF_DEG + N_NODES;
static constexpr size_t IOFF_CUR  = IOFF_RS_ + N_NODES + 1;
static constexpr size_t IOFF_PERM = IOFF_CUR + N_NODES;
__device__ int g_iscratch[IOFF_PERM + NE];

// ---------------- CSR build kernels ----------------
__global__ void zero_int_kernel(int* __restrict__ p, int n) {
    int i = blockIdx.x * blockDim.x + threadIdx.x;
    if (i < n) p[i] = 0;
}
__global__ void hist_kernel(const int* __restrict__ edst, int* __restrict__ deg) {
    int e = blockIdx.x * blockDim.x + threadIdx.x;
    if (e < NE) atomicAdd(&deg[edst[e]], 1);
}
__global__ __launch_bounds__(512)
void scan_kernel(const int* __restrict__ deg, int* __restrict__ row_start,
                 int* __restrict__ cursor) {
    __shared__ int part[512];
    int tid = threadIdx.x;
    int base = tid * 32;
    int loc[32];
    int s = 0;
#pragma unroll
    for (int j = 0; j < 32; j++) { loc[j] = s; s += deg[base + j]; }
    part[tid] = s;
    __syncthreads();
    for (int off = 1; off < 512; off <<= 1) {
        int v = (tid >= off) ? part[tid - off] : 0;
        __syncthreads();
        part[tid] += v;
        __syncthreads();
    }
    int pre = (tid > 0) ? part[tid - 1] : 0;
#pragma unroll
    for (int j = 0; j < 32; j++) {
        int v = pre + loc[j];
        row_start[base + j] = v;
        cursor[base + j] = v;
    }
    if (tid == 511) row_start[N_NODES] = part[511];
}
__global__ void scatter_kernel(const int* __restrict__ edst, int* __restrict__ cursor,
                               int* __restrict__ perm) {
    int e = blockIdx.x * blockDim.x + threadIdx.x;
    if (e < NE) {
        int pos = atomicAdd(&cursor[edst[e]], 1);
        perm[pos] = e;
    }
}

// ---------------- conversion kernels ----------------
__global__ __launch_bounds__(256)
void conv_node_kernel(const float* __restrict__ feat, const float* __restrict__ w2v,
                      __half* __restrict__ FA, __half* __restrict__ WA,
                      __half* __restrict__ NFA)
{
    int n = blockIdx.x, tid = threadIdx.x;
    float4 f = *(const float4*)(feat + (size_t)n * 1024 + tid * 4);
    __half2 h0 = __floats2half2_rn(f.x, f.y);
    __half2 h1 = __floats2half2_rn(f.z, f.w);
    uint2 u; u.x = *(uint32_t*)&h0; u.y = *(uint32_t*)&h1;
    *(uint2*)(FA + (size_t)n * 2048 + tid * 4) = u;
    if (tid < 75) {
        float4 w = *(const float4*)(w2v + (size_t)n * 300 + tid * 4);
        __half2 g0 = __floats2half2_rn(w.x, w.y);
        __half2 g1 = __floats2half2_rn(w.z, w.w);
        uint2 v; v.x = *(uint32_t*)&g0; v.y = *(uint32_t*)&g1;
        *(uint2*)(WA + (size_t)n * 608 + tid * 4) = v;
    } else if (tid == 75) {
        uint2 z = make_uint2(0, 0);
        *(uint2*)(WA + (size_t)n * 608 + 600) = z;
        *(uint2*)(WA + (size_t)n * 608 + 604) = z;
    } else if (tid == 76) {
        uint2 z = make_uint2(0, 0);
        *(uint2*)(NFA + (size_t)n * 1328 + 1324) = z;
    }
}

__global__ void conv_sfro_kernel(const float* __restrict__ s_f_ro, __half* __restrict__ sfroh)
{
    size_t i = (size_t)blockIdx.x * blockDim.x + threadIdx.x;   // pair index
    if (i >= (size_t)NE_RO * 8) return;
    float2 f = *(const float2*)(s_f_ro + i * 2);
    __half2 h = __floats2half2_rn(f.x, f.y);
    *(uint32_t*)(sfroh + i * 2) = *(uint32_t*)&h;
}

// ---------------- fp16 pack + mma + cp.async helpers ----------------
__device__ __forceinline__ uint32_t f16_pack(float f0, float f1) {
    __half2 h = __floats2half2_rn(f0, f1);
    return *(uint32_t*)&h;
}
__device__ __forceinline__ void mma_f16(float* c, const uint32_t* a, const uint32_t* b) {
    asm volatile("mma.sync.aligned.m16n8k16.row.col.f32.f16.f16.f32 "
        "{%0,%1,%2,%3}, {%4,%5,%6,%7}, {%8,%9}, {%0,%1,%2,%3};"
        : "+f"(c[0]), "+f"(c[1]), "+f"(c[2]), "+f"(c[3])
        : "r"(a[0]), "r"(a[1]), "r"(a[2]), "r"(a[3]), "r"(b[0]), "r"(b[1]));
}
__device__ __forceinline__ uint32_t smem_u32(const void* p) {
    uint32_t a;
    asm("{ .reg .u64 t; cvta.to.shared.u64 t, %1; cvt.u32.u64 %0, t; }" : "=r"(a) : "l"(p));
    return a;
}
__device__ __forceinline__ void cp_async16(uint32_t dst, const void* src, int src_bytes) {
    asm volatile("cp.async.cg.shared.global [%0], [%1], 16, %2;"
                 :: "r"(dst), "l"(src), "r"(src_bytes) : "memory");
}
__device__ __forceinline__ void cp_async4(uint32_t dst, const void* src, int src_bytes) {
    asm volatile("cp.async.ca.shared.global [%0], [%1], 4, %2;"
                 :: "r"(dst), "l"(src), "r"(src_bytes) : "memory");
}
#define CP_COMMIT() asm volatile("cp.async.commit_group;" ::: "memory")
#define CP_WAIT(N)  asm volatile("cp.async.wait_group %0;" :: "n"(N) : "memory")

// ---------------- fp16-A GEMM (R9 body, unchanged) ----------------
struct GArgs {
    const __half* A; int lda; int K;
    const float* B1; const float* B2; int KB1;
    void* C; int ldc;
};

static constexpr int A_PAD_H   = 40;
static constexpr int A_BYTES   = 128 * A_PAD_H * 2;        // 10240
static constexpr int B_PAD     = 132;
static constexpr int B_BYTES   = 32 * B_PAD * 4;           // 16896
static constexpr int STG_BYTES = A_BYTES + B_BYTES;        // 27136
static constexpr int STAGES    = 3;
static constexpr int GM_SMEM   = STAGES * STG_BYTES;       // 81408

__global__ __launch_bounds__(256)
void gemm_h(GArgs za, GArgs zb, int ldb, const float* __restrict__ bias,
            int Nn, int doRelu, int outHalf)
{
    extern __shared__ char smc[];
    GArgs ga = (blockIdx.z == 0) ? za : zb;

    const int tid  = threadIdx.x;
    const int wid  = tid >> 5;
    const int lane = tid & 31;
    const int g    = lane >> 2;
    const int t    = lane & 3;
    const int m0   = blockIdx.y * 128;
    const int n0   = blockIdx.x * 128;
    const int K    = ga.K;
    const int nT   = (K + 31) / 32;
    const int wm   = wid & 3;
    const int wn   = wid >> 2;
    const bool b_vec = ((ldb & 3) == 0);

    const uint32_t smb = smem_u32(smc);

    float acc[2][8][4];
#pragma unroll
    for (int i = 0; i < 2; i++)
#pragma unroll
        for (int j = 0; j < 8; j++)
#pragma unroll
            for (int k = 0; k < 4; k++) acc[i][j][k] = 0.f;

    auto issue_load = [&](int tt, int buf) {
        if (tt < nT) {
            const int k0 = tt * 32;
            uint32_t Ab = smb + (uint32_t)buf * STG_BYTES;
            uint32_t Bb_ = Ab + A_BYTES;
#pragma unroll
            for (int i = 0; i < 2; i++) {
                int idx = i * 256 + tid;
                int row = idx >> 2, c8 = idx & 3;
                int kb = k0 + c8 * 8;
                const __half* src = ga.A;
                int sz = 0;
                if (kb < K) { src = ga.A + (size_t)(m0 + row) * ga.lda + kb; sz = 16; }
                cp_async16(Ab + (uint32_t)(row * (A_PAD_H * 2) + c8 * 16), src, sz);
            }
            if (b_vec) {
#pragma unroll
                for (int i = 0; i < 4; i++) {
                    int idx = i * 256 + tid;
                    int k = idx >> 5, n4 = idx & 31;
                    int kg = k0 + k;
                    int nb4 = n0 + n4 * 4;
                    const float* src = ga.B1;
                    int sz = 0;
                    if (kg < K && nb4 + 3 < Nn) {
                        src = (kg < ga.KB1) ? (ga.B1 + (size_t)kg * ldb + nb4)
                                            : (ga.B2 + (size_t)(kg - ga.KB1) * ldb + nb4);
                        sz = 16;
                    }
                    cp_async16(Bb_ + (uint32_t)(k * B_PAD + n4 * 4) * 4, src, sz);
                }
            } else {
#pragma unroll
                for (int i = 0; i < 4; i++) {
                    int idx = i * 256 + tid;
                    int k = idx >> 5, n4 = idx & 31;
                    int kg = k0 + k;
#pragma unroll
                    for (int j = 0; j < 4; j++) {
                        int nn = n0 + n4 * 4 + j;
                        const float* src = ga.B1;
                        int sz = 0;
                        if (kg < K && nn < Nn) {
                            src = (kg < ga.KB1) ? (ga.B1 + (size_t)kg * ldb + nn)
                                                : (ga.B2 + (size_t)(kg - ga.KB1) * ldb + nn);
                            sz = 4;
                        }
                        cp_async4(Bb_ + (uint32_t)(k * B_PAD + n4 * 4 + j) * 4, src, sz);
                    }
                }
            }
        }
        CP_COMMIT();
    };

    auto compute = [&](int buf) {
        const __half* As = (const __half*)(smc + buf * STG_BYTES) + (wm * 32) * A_PAD_H;
        const float*  Bs = (const float*)(smc + buf * STG_BYTES + A_BYTES) + wn * 64;
#pragma unroll
        for (int ks = 0; ks < 2; ks++) {
            uint32_t ah[2][4];
#pragma unroll
            for (int mb = 0; mb < 2; mb++) {
#pragma unroll
                for (int r = 0; r < 4; r++) {
                    int rowq = mb * 16 + g + (r & 1) * 8;
                    int kq   = ks * 16 + t * 2 + (r >> 1) * 8;
                    ah[mb][r] = *(const uint32_t*)(As + rowq * A_PAD_H + kq);
                }
            }
            uint32_t bh[8][2];
#pragma unroll
            for (int nb = 0; nb < 8; nb++) {
#pragma unroll
                for (int r = 0; r < 2; r++) {
                    int kq = ks * 16 + t * 2 + r * 8;
                    float f0 = Bs[kq * B_PAD + nb * 8 + g];
                    float f1 = Bs[(kq + 1) * B_PAD + nb * 8 + g];
                    bh[nb][r] = f16_pack(f0, f1);
                }
            }
#pragma unroll
            for (int mb = 0; mb < 2; mb++) {
#pragma unroll
                for (int nb = 0; nb < 8; nb++) {
                    mma_f16(acc[mb][nb], ah[mb], bh[nb]);
                }
            }
        }
    };

#pragma unroll
    for (int s = 0; s < STAGES - 1; s++) issue_load(s, s);

    for (int tt = 0; tt < nT; tt++) {
        issue_load(tt + STAGES - 1, (tt + STAGES - 1) % STAGES);
        CP_WAIT(STAGES - 1);
        __syncthreads();
        compute(tt % STAGES);
        __syncthreads();
    }

    // ---- epilogue ----
#pragma unroll
    for (int mb = 0; mb < 2; mb++) {
#pragma unroll
        for (int nb = 0; nb < 8; nb++) {
            int n = n0 + wn * 64 + nb * 8 + t * 2;
            float bv0 = 0.f, bv1 = 0.f;
            if (bias) {
                if (n     < Nn) bv0 = bias[n];
                if (n + 1 < Nn) bv1 = bias[n + 1];
            }
#pragma unroll
            for (int h = 0; h < 2; h++) {
                int m = m0 + wm * 32 + mb * 16 + g + h * 8;
                float v0 = acc[mb][nb][h * 2 + 0] + bv0;
                float v1 = acc[mb][nb][h * 2 + 1] + bv1;
                if (doRelu) { v0 = fmaxf(v0, 0.f); v1 = fmaxf(v1, 0.f); }
                if (outHalf) {
                    if (n < Nn) {
                        __half2 hv = __floats2half2_rn(v0, v1);
                        *(uint32_t*)((__half*)ga.C + (size_t)m * ga.ldc + n) = *(uint32_t*)&hv;
                    }
                } else {
                    float* cp = (float*)ga.C + (size_t)m * ga.ldc + n;
                    if (n     < Nn) cp[0] = v0;
                    if (n + 1 < Nn) cp[1] = v1;
                }
            }
        }
    }
}

// ---------------- appearance aggregation: inline spatial term, persistent blocks ----------------
// agg[n] = mean over in-edges of relu(P1[src] + (s_f[e] @ Ws) + P2[n] + b_e)
// Ws (fp32, [16][1024]) held in registers: thread tid owns columns tid*4..tid*4+3.
static constexpr int AGG_GRID = 2048;
static constexpr int CHUNK    = 16;

__global__ __launch_bounds__(256)
void agg_app_kernel(const __half* __restrict__ P1h, const __half* __restrict__ P2h,
                    const float* __restrict__ b_e, const float* __restrict__ Wsp,
                    const float* __restrict__ s_f,
                    const int* __restrict__ esrc, const int* __restrict__ perm,
                    const int* __restrict__ row_start, __half* __restrict__ FA)
{
    const int tid = threadIdx.x;
    __shared__ float sfs[CHUNK][DS];
    __shared__ int   ss[CHUNK];

    // spatial weight columns for this thread (64 regs), loaded once per block
    float4 w[DS];
#pragma unroll
    for (int k = 0; k < DS; k++)
        w[k] = *(const float4*)(Wsp + (size_t)k * 1024 + tid * 4);

    float4 be = ((const float4*)b_e)[tid];

    for (int n = blockIdx.x; n < N_NODES; n += AGG_GRID) {
        const int start = row_start[n];
        const int nb = row_start[n + 1] - start;

        uint2 p2 = *(const uint2*)(P2h + (size_t)n * 1024 + tid * 4);
        float2 b0 = __half22float2(*(__half2*)&p2.x);
        float2 b1 = __half22float2(*(__half2*)&p2.y);
        float bx = b0.x + be.x, by = b0.y + be.y, bz = b1.x + be.z, bw = b1.y + be.w;

        float4 acc = make_float4(0.f, 0.f, 0.f, 0.f);
        for (int i0 = 0; i0 < nb; i0 += CHUNK) {
            int cnt = min(CHUNK, nb - i0);
            __syncthreads();
            if (tid < cnt)
                ss[tid] = __ldg(&esrc[__ldg(&perm[start + i0 + tid])]);
            if (tid < cnt * DS) {
                int j = tid >> 4, k = tid & 15;
                int e = __ldg(&perm[start + i0 + j]);
                sfs[j][k] = __ldg(&s_f[(size_t)e * DS + k]);
            }
            __syncthreads();
            for (int j = 0; j < cnt; j++) {
                int s = ss[j];
                uint2 a = *(const uint2*)(P1h + (size_t)s * 1024 + tid * 4);
                float2 a0 = __half22float2(*(__half2*)&a.x);
                float2 a1 = __half22float2(*(__half2*)&a.y);
                float vx = a0.x + bx, vy = a0.y + by, vz = a1.x + bz, vw = a1.y + bw;
#pragma unroll
                for (int k = 0; k < DS; k++) {
                    float f = sfs[j][k];
                    vx += f * w[k].x; vy += f * w[k].y; vz += f * w[k].z; vw += f * w[k].w;
                }
                acc.x += fmaxf(vx, 0.f);
                acc.y += fmaxf(vy, 0.f);
                acc.z += fmaxf(vz, 0.f);
                acc.w += fmaxf(vw, 0.f);
            }
        }
        float inv = 1.0f / (float)max(nb, 1);
        __half2 o0 = __floats2half2_rn(acc.x * inv, acc.y * inv);
        __half2 o1 = __floats2half2_rn(acc.z * inv, acc.w * inv);
        uint2 o; o.x = *(uint32_t*)&o0; o.y = *(uint32_t*)&o1;
        *(uint2*)(FA + (size_t)n * 2048 + 1024 + tid * 4) = o;
    }
}

// ---------------- language aggregation (CSR gather, fp16 data) ----------------
__global__ __launch_bounds__(96)
void agg_lang_kernel(const __half* __restrict__ Q1h, const __half* __restrict__ Q2h,
                     const float* __restrict__ b_el,
                     const int* __restrict__ esrc, const int* __restrict__ perm,
                     const int* __restrict__ row_start, __half* __restrict__ WA)
{
    const int n = blockIdx.x;
    const int c4 = threadIdx.x;
    if (c4 >= DL / 4) return;
    const int start = row_start[n];
    const int nb = row_start[n + 1] - start;

    uint2 q2 = *(const uint2*)(Q2h + (size_t)n * 304 + c4 * 4);
    float2 b0 = __half22float2(*(__half2*)&q2.x);
    float2 b1 = __half22float2(*(__half2*)&q2.y);
    float4 be = ((const float4*)b_el)[c4];
    float bx = b0.x + be.x, by = b0.y + be.y, bz = b1.x + be.z, bw = b1.y + be.w;

    float4 acc = make_float4(0.f, 0.f, 0.f, 0.f);
#pragma unroll 2
    for (int i = 0; i < nb; i++) {
        int e = __ldg(&perm[start + i]);
        int s = __ldg(&esrc[e]);
        uint2 a = *(const uint2*)(Q1h + (size_t)s * 304 + c4 * 4);
        float2 a0 = __half22float2(*(__half2*)&a.x);
        float2 a1 = __half22float2(*(__half2*)&a.y);
        acc.x += fmaxf(a0.x + bx, 0.f);
        acc.y += fmaxf(a0.y + by, 0.f);
        acc.z += fmaxf(a1.x + bz, 0.f);
        acc.w += fmaxf(a1.y + bw, 0.f);
    }
    float inv = 1.0f / (float)max(nb, 1);
    __half2 o0 = __floats2half2_rn(acc.x * inv, acc.y * inv);
    __half2 o1 = __floats2half2_rn(acc.z * inv, acc.w * inv);
    uint2 o; o.x = *(uint32_t*)&o0; o.y = *(uint32_t*)&o1;
    *(uint2*)(WA + (size_t)n * 608 + 300 + c4 * 4) = o;
}

// ---------------- readout ----------------
__global__ __launch_bounds__(128)
void readout_kernel(const float* __restrict__ Rd, const float* __restrict__ Rs,
                    const float* __restrict__ SPro,
                    const int* __restrict__ rsrc, const int* __restrict__ rdst,
                    float* __restrict__ pred)
{
    int e = blockIdx.x;
    int c = threadIdx.x;
    if (c >= NC) return;
    int s = rsrc[e];
    int d = rdst[e];
    pred[(size_t)e * NC + c] = Rd[(size_t)d * NC + c] + Rs[(size_t)s * NC + c]
                             + SPro[(size_t)e * NC + c];
}

// ---------------- host launcher ----------------
extern "C" void kernel_launch(void* const* d_in, const int* in_sizes, int n_in,
                              void* d_out, int out_size)
{
    const float* feat   = (const float*)d_in[0];
    const float* w2v    = (const float*)d_in[1];
    const float* s_f    = (const float*)d_in[2];
    const float* s_f_ro = (const float*)d_in[3];
    const float* W_e    = (const float*)d_in[4];
    const float* b_e    = (const float*)d_in[5];
    const float* W_el   = (const float*)d_in[6];
    const float* b_el   = (const float*)d_in[7];
    const float* W_nu   = (const float*)d_in[8];
    const float* b_nu   = (const float*)d_in[9];
    const float* W_nul  = (const float*)d_in[10];
    const float* b_nul  = (const float*)d_in[11];
    const float* W_p    = (const float*)d_in[12];
    const float* b_p    = (const float*)d_in[13];
    const int* esrc = (const int*)d_in[14];
    const int* edst = (const int*)d_in[15];
    const int* rsrc = (const int*)d_in[16];
    const int* rdst = (const int*)d_in[17];
    float* pred = (float*)d_out;

    float* sc = nullptr;
    cudaGetSymbolAddress((void**)&sc, g_scratch);
    __half* hs = nullptr;
    cudaGetSymbolAddress((void**)&hs, g_hscratch);
    int* isc = nullptr;
    cudaGetSymbolAddress((void**)&isc, g_iscratch);

    float* RD   = sc + OFF_RD;
    float* RS   = sc + OFF_RS;
    float* SPRO = sc + OFF_SPRO;

    __half* FA    = hs + HOFF_FA;
    __half* WA    = hs + HOFF_WA;
    __half* NFA   = hs + HOFF_NFA;
    __half* P1h   = hs + HOFF_P1;
    __half* P2h   = hs + HOFF_P2;
    __half* Q1h   = hs + HOFF_Q1;
    __half* Q2h   = hs + HOFF_Q2;
    __half* sfroh = hs + HOFF_SFRO;

    int* deg  = isc + IOFF_DEG;
    int* rows = isc + IOFF_RS_;
    int* cur  = isc + IOFF_CUR;
    int* perm = isc + IOFF_PERM;

    cudaFuncSetAttribute(gemm_h, cudaFuncAttributeMaxDynamicSharedMemorySize, GM_SMEM);

    const float* Wsp = W_e + (size_t)(2 * D) * D;      // spatial rows of W_e
    const float* Wp3 = W_p + (size_t)(D + DL) * NC;    // spatial rows of W_p

    // ---- conversions ----
    conv_node_kernel<<<N_NODES, 256>>>(feat, w2v, FA, WA, NFA);
    conv_sfro_kernel<<<(NE_RO * 8 + 255) / 256, 256>>>(s_f_ro, sfroh);

    // ---- CSR build (by dst) ----
    zero_int_kernel<<<(N_NODES + 255) / 256, 256>>>(deg, N_NODES);
    hist_kernel<<<NE / 256, 256>>>(edst, deg);
    scan_kernel<<<1, 512>>>(deg, rows, cur);
    scatter_kernel<<<NE / 256, 256>>>(edst, cur, perm);

    dim3 blk(256);
    const int BIG = 1 << 28;

    // ---- SPro[e] = s_f_ro @ Wp3 + b_p -> fp32 [NE_RO,117] ----
    {
        GArgs a{sfroh, 16, 16, Wp3, Wp3, BIG, SPRO, NC};
        gemm_h<<<dim3(1, 256, 1), blk, GM_SMEM>>>(a, a, NC, b_p, NC, 0, 0);
    }
    // ---- node-level pre-projections (siblings merged via grid.z) ----
    {
        GArgs a{FA, 2048, 1024, W_e, W_e, BIG, P1h, 1024};
        GArgs b{FA, 2048, 1024, W_e + (size_t)D * D, W_e, BIG, P2h, 1024};
        gemm_h<<<dim3(8, 128, 2), blk, GM_SMEM>>>(a, b, D, nullptr, D, 0, 1);
    }
    {
        GArgs a{WA, 608, 300, W_el, W_el, BIG, Q1h, 304};
        GArgs b{WA, 608, 300, W_el + (size_t)DL * DL, W_el, BIG, Q2h, 304};
        gemm_h<<<dim3(3, 128, 2), blk, GM_SMEM>>>(a, b, DL, nullptr, DL, 0, 1);
    }

    // ---- aggregation (gather, no atomics; spatial term inline) ----
    agg_app_kernel<<<AGG_GRID, 256>>>(P1h, P2h, b_e, Wsp, s_f, esrc, perm, rows, FA);
    agg_lang_kernel<<<N_NODES, 96>>>(Q1h, Q2h, b_el, esrc, perm, rows, WA);

    // ---- node updates ----
    {
        GArgs a{FA, 2048, 2048, W_nu, W_nu, BIG, NFA, 1328};
        gemm_h<<<dim3(8, 128, 1), blk, GM_SMEM>>>(a, a, D, b_nu, D, 1, 1);
    }
    {
        GArgs a{WA, 608, 600, W_nul, W_nul, BIG, NFA + 1024, 1328};
        gemm_h<<<dim3(3, 128, 1), blk, GM_SMEM>>>(a, a, DL, b_nul, DL, 1, 1);
    }

    // ---- predictor pre-projections (RD & RS merged; RS via two-segment B) ----
    {
        GArgs a{NFA, 1328, 1324, W_p, W_p, BIG, RD, NC};
        GArgs b{NFA, 1328, 1324,
                W_p + (size_t)(D + DL + DS + DL) * NC,   // NF part: rows 1640..2663
                W_p + (size_t)(D + DL + DS) * NC,        // NFL part: rows 1340..1639
                1024, RS, NC};
        gemm_h<<<dim3(1, 128, 2), blk, GM_SMEM>>>(a, b, NC, nullptr, NC, 0, 0);
    }

    // ---- final edge readout ----
    readout_kernel<<<NE_RO, 128>>>(RD, RS, SPRO, rsrc, rdst, pred);
}

// round 13
// speedup vs baseline: 1.0945x; 1.0147x over previous
#include <cuda_runtime.h>
#include <cuda_fp16.h>
#include <cstdint>
#include <cstddef>

// ---------------- problem dimensions ----------------
static constexpr int N_NODES = 16384;
static constexpr int NE      = 131072;
static constexpr int NE_RO   = 32768;
static constexpr int D       = 1024;
static constexpr int DL      = 300;
static constexpr int DS      = 16;
static constexpr int NC      = 117;

// ---------------- fp32 scratch (readout precursors) ----------------
static constexpr size_t SZ_NC   = (size_t)N_NODES * NC;
static constexpr size_t SZ_SPRO = (size_t)NE_RO * NC;
static constexpr size_t OFF_RD   = 0;
static constexpr size_t OFF_RS   = OFF_RD + SZ_NC;
static constexpr size_t OFF_SPRO = OFF_RS + SZ_NC;
static constexpr size_t TOTAL_F32 = OFF_SPRO + SZ_SPRO;
__device__ float g_scratch[TOTAL_F32];

// ---------------- fp16 scratch ----------------
static constexpr size_t HOFF_FA   = 0;                               // [N][2048] = [feat|AGG]
static constexpr size_t HSZ_FA    = (size_t)N_NODES * 2048;
static constexpr size_t HOFF_WA   = HOFF_FA + HSZ_FA;                // [N][608]  = [w2v|AGGL|pad]
static constexpr size_t HSZ_WA    = (size_t)N_NODES * 608;
static constexpr size_t HOFF_NFA  = HOFF_WA + HSZ_WA;                // [N][1328] = [NF|NFL|pad]
static constexpr size_t HSZ_NFA   = (size_t)N_NODES * 1328;
static constexpr size_t HOFF_P1   = HOFF_NFA + HSZ_NFA;
static constexpr size_t HSZ_P     = (size_t)N_NODES * 1024;
static constexpr size_t HOFF_P2   = HOFF_P1 + HSZ_P;
static constexpr size_t HOFF_Q1   = HOFF_P2 + HSZ_P;
static constexpr size_t HSZ_Q     = (size_t)N_NODES * 304;
static constexpr size_t HOFF_Q2   = HOFF_Q1 + HSZ_Q;
static constexpr size_t HOFF_SP   = HOFF_Q2 + HSZ_Q;                 // permuted SP: row i <-> edge perm[i]
static constexpr size_t HSZ_SP    = (size_t)NE * 1024;
static constexpr size_t HOFF_SFH  = HOFF_SP + HSZ_SP;
static constexpr size_t HSZ_SFH   = (size_t)NE * 16;
static constexpr size_t HOFF_SFRO = HOFF_SFH + HSZ_SFH;
static constexpr size_t HSZ_SFRO  = (size_t)NE_RO * 16;
static constexpr size_t TOTAL_H   = HOFF_SFRO + HSZ_SFRO;
__device__ __half g_hscratch[TOTAL_H];

// int scratch
static constexpr size_t IOFF_DEG  = 0;
static constexpr size_t IOFF_RS_  = IOFF_DEG + N_NODES;
static constexpr size_t IOFF_CUR  = IOFF_RS_ + N_NODES + 1;
static constexpr size_t IOFF_PERM = IOFF_CUR + N_NODES;
__device__ int g_iscratch[IOFF_PERM + NE];

// ---------------- CSR build kernels ----------------
__global__ void zero_int_kernel(int* __restrict__ p, int n) {
    int i = blockIdx.x * blockDim.x + threadIdx.x;
    if (i < n) p[i] = 0;
}
__global__ void hist_kernel(const int* __restrict__ edst, int* __restrict__ deg) {
    int e = blockIdx.x * blockDim.x + threadIdx.x;
    if (e < NE) atomicAdd(&deg[edst[e]], 1);
}
__global__ __launch_bounds__(512)
void scan_kernel(const int* __restrict__ deg, int* __restrict__ row_start,
                 int* __restrict__ cursor) {
    __shared__ int part[512];
    int tid = threadIdx.x;
    int base = tid * 32;
    int loc[32];
    int s = 0;
#pragma unroll
    for (int j = 0; j < 32; j++) { loc[j] = s; s += deg[base + j]; }
    part[tid] = s;
    __syncthreads();
    for (int off = 1; off < 512; off <<= 1) {
        int v = (tid >= off) ? part[tid - off] : 0;
        __syncthreads();
        part[tid] += v;
        __syncthreads();
    }
    int pre = (tid > 0) ? part[tid - 1] : 0;
#pragma unroll
    for (int j = 0; j < 32; j++) {
        int v = pre + loc[j];
        row_start[base + j] = v;
        cursor[base + j] = v;
    }
    if (tid == 511) row_start[N_NODES] = part[511];
}
__global__ void scatter_kernel(const int* __restrict__ edst, int* __restrict__ cursor,
                               int* __restrict__ perm) {
    int e = blockIdx.x * blockDim.x + threadIdx.x;
    if (e < NE) {
        int pos = atomicAdd(&cursor[edst[e]], 1);
        perm[pos] = e;
    }
}

// ---------------- conversion kernels ----------------
__global__ __launch_bounds__(256)
void conv_node_kernel(const float* __restrict__ feat, const float* __restrict__ w2v,
                      __half* __restrict__ FA, __half* __restrict__ WA,
                      __half* __restrict__ NFA)
{
    int n = blockIdx.x, tid = threadIdx.x;
    float4 f = *(const float4*)(feat + (size_t)n * 1024 + tid * 4);
    __half2 h0 = __floats2half2_rn(f.x, f.y);
    __half2 h1 = __floats2half2_rn(f.z, f.w);
    uint2 u; u.x = *(uint32_t*)&h0; u.y = *(uint32_t*)&h1;
    *(uint2*)(FA + (size_t)n * 2048 + tid * 4) = u;
    if (tid < 75) {
        float4 w = *(const float4*)(w2v + (size_t)n * 300 + tid * 4);
        __half2 g0 = __floats2half2_rn(w.x, w.y);
        __half2 g1 = __floats2half2_rn(w.z, w.w);
        uint2 v; v.x = *(uint32_t*)&g0; v.y = *(uint32_t*)&g1;
        *(uint2*)(WA + (size_t)n * 608 + tid * 4) = v;
    } else if (tid == 75) {
        uint2 z = make_uint2(0, 0);
        *(uint2*)(WA + (size_t)n * 608 + 600) = z;
        *(uint2*)(WA + (size_t)n * 608 + 604) = z;
    } else if (tid == 76) {
        uint2 z = make_uint2(0, 0);
        *(uint2*)(NFA + (size_t)n * 1328 + 1324) = z;
    }
}

__global__ void conv_sf_kernel(const float* __restrict__ s_f, const float* __restrict__ s_f_ro,
                               __half* __restrict__ sfh, __half* __restrict__ sfroh)
{
    size_t i = (size_t)blockIdx.x * blockDim.x + threadIdx.x;
    size_t n1 = (size_t)NE * 8;
    size_t tot = n1 + (size_t)NE_RO * 8;
    if (i >= tot) return;
    if (i < n1) {
        float2 f = *(const float2*)(s_f + i * 2);
        __half2 h = __floats2half2_rn(f.x, f.y);
        *(uint32_t*)(sfh + i * 2) = *(uint32_t*)&h;
    } else {
        size_t j = i - n1;
        float2 f = *(const float2*)(s_f_ro + j * 2);
        __half2 h = __floats2half2_rn(f.x, f.y);
        *(uint32_t*)(sfroh + j * 2) = *(uint32_t*)&h;
    }
}

// ---------------- fp16 pack + mma + cp.async helpers ----------------
__device__ __forceinline__ uint32_t f16_pack(float f0, float f1) {
    __half2 h = __floats2half2_rn(f0, f1);
    return *(uint32_t*)&h;
}
__device__ __forceinline__ void mma_f16(float* c, const uint32_t* a, const uint32_t* b) {
    asm volatile("mma.sync.aligned.m16n8k16.row.col.f32.f16.f16.f32 "
        "{%0,%1,%2,%3}, {%4,%5,%6,%7}, {%8,%9}, {%0,%1,%2,%3};"
        : "+f"(c[0]), "+f"(c[1]), "+f"(c[2]), "+f"(c[3])
        : "r"(a[0]), "r"(a[1]), "r"(a[2]), "r"(a[3]), "r"(b[0]), "r"(b[1]));
}
__device__ __forceinline__ uint32_t smem_u32(const void* p) {
    uint32_t a;
    asm("{ .reg .u64 t; cvta.to.shared.u64 t, %1; cvt.u32.u64 %0, t; }" : "=r"(a) : "l"(p));
    return a;
}
__device__ __forceinline__ void cp_async16(uint32_t dst, const void* src, int src_bytes) {
    asm volatile("cp.async.cg.shared.global [%0], [%1], 16, %2;"
                 :: "r"(dst), "l"(src), "r"(src_bytes) : "memory");
}
__device__ __forceinline__ void cp_async4(uint32_t dst, const void* src, int src_bytes) {
    asm volatile("cp.async.ca.shared.global [%0], [%1], 4, %2;"
                 :: "r"(dst), "l"(src), "r"(src_bytes) : "memory");
}
#define CP_COMMIT() asm volatile("cp.async.commit_group;" ::: "memory")
#define CP_WAIT(N)  asm volatile("cp.async.wait_group %0;" :: "n"(N) : "memory")

// ---------------- fp16-A GEMM (R9 body + optional A-row permutation) ----------------
struct GArgs {
    const __half* A; int lda; int K;
    const float* B1; const float* B2; int KB1;
    void* C; int ldc;
    const int* Aperm;   // optional: A row i -> A[Aperm[i]]  (nullptr = identity)
};

static constexpr int A_PAD_H   = 40;
static constexpr int A_BYTES   = 128 * A_PAD_H * 2;        // 10240
static constexpr int B_PAD     = 132;
static constexpr int B_BYTES   = 32 * B_PAD * 4;           // 16896
static constexpr int STG_BYTES = A_BYTES + B_BYTES;        // 27136
static constexpr int STAGES    = 3;
static constexpr int GM_SMEM   = STAGES * STG_BYTES;       // 81408

__global__ __launch_bounds__(256)
void gemm_h(GArgs za, GArgs zb, int ldb, const float* __restrict__ bias,
            int Nn, int doRelu, int outHalf)
{
    extern __shared__ char smc[];
    GArgs ga = (blockIdx.z == 0) ? za : zb;

    const int tid  = threadIdx.x;
    const int wid  = tid >> 5;
    const int lane = tid & 31;
    const int g    = lane >> 2;
    const int t    = lane & 3;
    const int m0   = blockIdx.y * 128;
    const int n0   = blockIdx.x * 128;
    const int K    = ga.K;
    const int nT   = (K + 31) / 32;
    const int wm   = wid & 3;
    const int wn   = wid >> 2;
    const bool b_vec = ((ldb & 3) == 0);

    const uint32_t smb = smem_u32(smc);

    float acc[2][8][4];
#pragma unroll
    for (int i = 0; i < 2; i++)
#pragma unroll
        for (int j = 0; j < 8; j++)
#pragma unroll
            for (int k = 0; k < 4; k++) acc[i][j][k] = 0.f;

    auto issue_load = [&](int tt, int buf) {
        if (tt < nT) {
            const int k0 = tt * 32;
            uint32_t Ab = smb + (uint32_t)buf * STG_BYTES;
            uint32_t Bb_ = Ab + A_BYTES;
#pragma unroll
            for (int i = 0; i < 2; i++) {
                int idx = i * 256 + tid;
                int row = idx >> 2, c8 = idx & 3;
                int kb = k0 + c8 * 8;
                const __half* src = ga.A;
                int sz = 0;
                if (kb < K) {
                    int m = m0 + row;
                    if (ga.Aperm) m = __ldg(&ga.Aperm[m]);
                    src = ga.A + (size_t)m * ga.lda + kb; sz = 16;
                }
                cp_async16(Ab + (uint32_t)(row * (A_PAD_H * 2) + c8 * 16), src, sz);
            }
            if (b_vec) {
#pragma unroll
                for (int i = 0; i < 4; i++) {
                    int idx = i * 256 + tid;
                    int k = idx >> 5, n4 = idx & 31;
                    int kg = k0 + k;
                    int nb4 = n0 + n4 * 4;
                    const float* src = ga.B1;
                    int sz = 0;
                    if (kg < K && nb4 + 3 < Nn) {
                        src = (kg < ga.KB1) ? (ga.B1 + (size_t)kg * ldb + nb4)
                                            : (ga.B2 + (size_t)(kg - ga.KB1) * ldb + nb4);
                        sz = 16;
                    }
                    cp_async16(Bb_ + (uint32_t)(k * B_PAD + n4 * 4) * 4, src, sz);
                }
            } else {
#pragma unroll
                for (int i = 0; i < 4; i++) {
                    int idx = i * 256 + tid;
                    int k = idx >> 5, n4 = idx & 31;
                    int kg = k0 + k;
#pragma unroll
                    for (int j = 0; j < 4; j++) {
                        int nn = n0 + n4 * 4 + j;
                        const float* src = ga.B1;
                        int sz = 0;
                        if (kg < K && nn < Nn) {
                            src = (kg < ga.KB1) ? (ga.B1 + (size_t)kg * ldb + nn)
                                                : (ga.B2 + (size_t)(kg - ga.KB1) * ldb + nn);
                            sz = 4;
                        }
                        cp_async4(Bb_ + (uint32_t)(k * B_PAD + n4 * 4 + j) * 4, src, sz);
                    }
                }
            }
        }
        CP_COMMIT();
    };

    auto compute = [&](int buf) {
        const __half* As = (const __half*)(smc + buf * STG_BYTES) + (wm * 32) * A_PAD_H;
        const float*  Bs = (const float*)(smc + buf * STG_BYTES + A_BYTES) + wn * 64;
#pragma unroll
        for (int ks = 0; ks < 2; ks++) {
            uint32_t ah[2][4];
#pragma unroll
            for (int mb = 0; mb < 2; mb++) {
#pragma unroll
                for (int r = 0; r < 4; r++) {
                    int rowq = mb * 16 + g + (r & 1) * 8;
                    int kq   = ks * 16 + t * 2 + (r >> 1) * 8;
                    ah[mb][r] = *(const uint32_t*)(As + rowq * A_PAD_H + kq);
                }
            }
            uint32_t bh[8][2];
#pragma unroll
            for (int nb = 0; nb < 8; nb++) {
#pragma unroll
                for (int r = 0; r < 2; r++) {
                    int kq = ks * 16 + t * 2 + r * 8;
                    float f0 = Bs[kq * B_PAD + nb * 8 + g];
                    float f1 = Bs[(kq + 1) * B_PAD + nb * 8 + g];
                    bh[nb][r] = f16_pack(f0, f1);
                }
            }
#pragma unroll
            for (int mb = 0; mb < 2; mb++) {
#pragma unroll
                for (int nb = 0; nb < 8; nb++) {
                    mma_f16(acc[mb][nb], ah[mb], bh[nb]);
                }
            }
        }
    };

#pragma unroll
    for (int s = 0; s < STAGES - 1; s++) issue_load(s, s);

    for (int tt = 0; tt < nT; tt++) {
        issue_load(tt + STAGES - 1, (tt + STAGES - 1) % STAGES);
        CP_WAIT(STAGES - 1);
        __syncthreads();
        compute(tt % STAGES);
        __syncthreads();
    }

    // ---- epilogue ----
#pragma unroll
    for (int mb = 0; mb < 2; mb++) {
#pragma unroll
        for (int nb = 0; nb < 8; nb++) {
            int n = n0 + wn * 64 + nb * 8 + t * 2;
            float bv0 = 0.f, bv1 = 0.f;
            if (bias) {
                if (n     < Nn) bv0 = bias[n];
                if (n + 1 < Nn) bv1 = bias[n + 1];
            }
#pragma unroll
            for (int h = 0; h < 2; h++) {
                int m = m0 + wm * 32 + mb * 16 + g + h * 8;
                float v0 = acc[mb][nb][h * 2 + 0] + bv0;
                float v1 = acc[mb][nb][h * 2 + 1] + bv1;
                if (doRelu) { v0 = fmaxf(v0, 0.f); v1 = fmaxf(v1, 0.f); }
                if (outHalf) {
                    if (n < Nn) {
                        __half2 hv = __floats2half2_rn(v0, v1);
                        *(uint32_t*)((__half*)ga.C + (size_t)m * ga.ldc + n) = *(uint32_t*)&hv;
                    }
                } else {
                    float* cp = (float*)ga.C + (size_t)m * ga.ldc + n;
                    if (n     < Nn) cp[0] = v0;
                    if (n + 1 < Nn) cp[1] = v1;
                }
            }
        }
    }
}

// ---------------- appearance aggregation (CSR gather; SP pre-permuted) ----------------
// SPp row (start+i) already corresponds to edge perm[start+i] -> sequential reads.
__global__ __launch_bounds__(256)
void agg_app_kernel(const __half* __restrict__ P1h, const __half* __restrict__ P2h,
                    const __half* __restrict__ SPp, const float* __restrict__ b_e,
                    const int* __restrict__ esrc, const int* __restrict__ perm,
                    const int* __restrict__ row_start, __half* __restrict__ FA)
{
    const int n = blockIdx.x;
    const int tid = threadIdx.x;
    const int start = row_start[n];
    const int nb = row_start[n + 1] - start;

    uint2 p2 = *(const uint2*)(P2h + (size_t)n * 1024 + tid * 4);
    float2 b0 = __half22float2(*(__half2*)&p2.x);
    float2 b1 = __half22float2(*(__half2*)&p2.y);
    float4 be = ((const float4*)b_e)[tid];
    float bx = b0.x + be.x, by = b0.y + be.y, bz = b1.x + be.z, bw = b1.y + be.w;

    float4 acc = make_float4(0.f, 0.f, 0.f, 0.f);
#pragma unroll 2
    for (int i = 0; i < nb; i++) {
        int e = __ldg(&perm[start + i]);
        int s = __ldg(&esrc[e]);
        uint2 a = *(const uint2*)(P1h + (size_t)s * 1024 + tid * 4);
        uint2 c = *(const uint2*)(SPp + (size_t)(start + i) * 1024 + tid * 4);
        float2 a0 = __half22float2(*(__half2*)&a.x);
        float2 a1 = __half22float2(*(__half2*)&a.y);
        float2 c0 = __half22float2(*(__half2*)&c.x);
        float2 c1 = __half22float2(*(__half2*)&c.y);
        acc.x += fmaxf(a0.x + c0.x + bx, 0.f);
        acc.y += fmaxf(a0.y + c0.y + by, 0.f);
        acc.z += fmaxf(a1.x + c1.x + bz, 0.f);
        acc.w += fmaxf(a1.y + c1.y + bw, 0.f);
    }
    float inv = 1.0f / (float)max(nb, 1);
    __half2 o0 = __floats2half2_rn(acc.x * inv, acc.y * inv);
    __half2 o1 = __floats2half2_rn(acc.z * inv, acc.w * inv);
    uint2 o; o.x = *(uint32_t*)&o0; o.y = *(uint32_t*)&o1;
    *(uint2*)(FA + (size_t)n * 2048 + 1024 + tid * 4) = o;
}

// ---------------- language aggregation (CSR gather, fp16 data) ----------------
__global__ __launch_bounds__(96)
void agg_lang_kernel(const __half* __restrict__ Q1h, const __half* __restrict__ Q2h,
                     const float* __restrict__ b_el,
                     const int* __restrict__ esrc, const int* __restrict__ perm,
                     const int* __restrict__ row_start, __half* __restrict__ WA)
{
    const int n = blockIdx.x;
    const int c4 = threadIdx.x;
    if (c4 >= DL / 4) return;
    const int start = row_start[n];
    const int nb = row_start[n + 1] - start;

    uint2 q2 = *(const uint2*)(Q2h + (size_t)n * 304 + c4 * 4);
    float2 b0 = __half22float2(*(__half2*)&q2.x);
    float2 b1 = __half22float2(*(__half2*)&q2.y);
    float4 be = ((const float4*)b_el)[c4];
    float bx = b0.x + be.x, by = b0.y + be.y, bz = b1.x + be.z, bw = b1.y + be.w;

    float4 acc = make_float4(0.f, 0.f, 0.f, 0.f);
#pragma unroll 2
    for (int i = 0; i < nb; i++) {
        int e = __ldg(&perm[start + i]);
        int s = __ldg(&esrc[e]);
        uint2 a = *(const uint2*)(Q1h + (size_t)s * 304 + c4 * 4);
        float2 a0 = __half22float2(*(__half2*)&a.x);
        float2 a1 = __half22float2(*(__half2*)&a.y);
        acc.x += fmaxf(a0.x + bx, 0.f);
        acc.y += fmaxf(a0.y + by, 0.f);
        acc.z += fmaxf(a1.x + bz, 0.f);
        acc.w += fmaxf(a1.y + bw, 0.f);
    }
    float inv = 1.0f / (float)max(nb, 1);
    __half2 o0 = __floats2half2_rn(acc.x * inv, acc.y * inv);
    __half2 o1 = __floats2half2_rn(acc.z * inv, acc.w * inv);
    uint2 o; o.x = *(uint32_t*)&o0; o.y = *(uint32_t*)&o1;
    *(uint2*)(WA + (size_t)n * 608 + 300 + c4 * 4) = o;
}

// ---------------- readout ----------------
__global__ __launch_bounds__(128)
void readout_kernel(const float* __restrict__ Rd, const float* __restrict__ Rs,
                    const float* __restrict__ SPro,
                    const int* __restrict__ rsrc, const int* __restrict__ rdst,
                    float* __restrict__ pred)
{
    int e = blockIdx.x;
    int c = threadIdx.x;
    if (c >= NC) return;
    int s = rsrc[e];
    int d = rdst[e];
    pred[(size_t)e * NC + c] = Rd[(size_t)d * NC + c] + Rs[(size_t)s * NC + c]
                             + SPro[(size_t)e * NC + c];
}

// ---------------- host launcher ----------------
extern "C" void kernel_launch(void* const* d_in, const int* in_sizes, int n_in,
                              void* d_out, int out_size)
{
    const float* feat   = (const float*)d_in[0];
    const float* w2v    = (const float*)d_in[1];
    const float* s_f    = (const float*)d_in[2];
    const float* s_f_ro = (const float*)d_in[3];
    const float* W_e    = (const float*)d_in[4];
    const float* b_e    = (const float*)d_in[5];
    const float* W_el   = (const float*)d_in[6];
    const float* b_el   = (const float*)d_in[7];
    const float* W_nu   = (const float*)d_in[8];
    const float* b_nu   = (const float*)d_in[9];
    const float* W_nul  = (const float*)d_in[10];
    const float* b_nul  = (const float*)d_in[11];
    const float* W_p    = (const float*)d_in[12];
    const float* b_p    = (const float*)d_in[13];
    const int* esrc = (const int*)d_in[14];
    const int* edst = (const int*)d_in[15];
    const int* rsrc = (const int*)d_in[16];
    const int* rdst = (const int*)d_in[17];
    float* pred = (float*)d_out;

    float* sc = nullptr;
    cudaGetSymbolAddress((void**)&sc, g_scratch);
    __half* hs = nullptr;
    cudaGetSymbolAddress((void**)&hs, g_hscratch);
    int* isc = nullptr;
    cudaGetSymbolAddress((void**)&isc, g_iscratch);

    float* RD   = sc + OFF_RD;
    float* RS   = sc + OFF_RS;
    float* SPRO = sc + OFF_SPRO;

    __half* FA    = hs + HOFF_FA;
    __half* WA    = hs + HOFF_WA;
    __half* NFA   = hs + HOFF_NFA;
    __half* P1h   = hs + HOFF_P1;
    __half* P2h   = hs + HOFF_P2;
    __half* Q1h   = hs + HOFF_Q1;
    __half* Q2h   = hs + HOFF_Q2;
    __half* SPh   = hs + HOFF_SP;
    __half* sfh   = hs + HOFF_SFH;
    __half* sfroh = hs + HOFF_SFRO;

    int* deg  = isc + IOFF_DEG;
    int* rows = isc + IOFF_RS_;
    int* cur  = isc + IOFF_CUR;
    int* perm = isc + IOFF_PERM;

    cudaFuncSetAttribute(gemm_h, cudaFuncAttributeMaxDynamicSharedMemorySize, GM_SMEM);

    const float* Ws  = W_e + (size_t)(2 * D) * D;      // spatial rows of W_e, stride D
    const float* Wp3 = W_p + (size_t)(D + DL) * NC;    // spatial rows of W_p

    // ---- conversions ----
    conv_node_kernel<<<N_NODES, 256>>>(feat, w2v, FA, WA, NFA);
    {
        size_t pairs = ((size_t)NE + NE_RO) * 8;
        conv_sf_kernel<<<(unsigned)((pairs + 255) / 256), 256>>>(s_f, s_f_ro, sfh, sfroh);
    }

    // ---- CSR build (by dst) ----
    zero_int_kernel<<<(N_NODES + 255) / 256, 256>>>(deg, N_NODES);
    hist_kernel<<<NE / 256, 256>>>(edst, deg);
    scan_kernel<<<1, 512>>>(deg, rows, cur);
    scatter_kernel<<<NE / 256, 256>>>(edst, cur, perm);

    dim3 blk(256);
    const int BIG = 1 << 28;

    // ---- spatial pre-projections ----
    {   // SPp[i] = s_f[perm[i]] @ Ws  -> fp16 [NE,1024], CSR order (needs perm)
        GArgs a{sfh, 16, 16, Ws, Ws, BIG, SPh, 1024, perm};
        gemm_h<<<dim3(8, NE / 128, 1), blk, GM_SMEM>>>(a, a, D, nullptr, D, 0, 1);
    }
    {   // SPro[e] = s_f_ro @ Wp3 + b_p -> fp32 [NE_RO,117]
        GArgs a{sfroh, 16, 16, Wp3, Wp3, BIG, SPRO, NC};
        gemm_h<<<dim3(1, 256, 1), blk, GM_SMEM>>>(a, a, NC, b_p, NC, 0, 0);
    }

    // ---- node-level pre-projections ----
    {   // P1 = feat @ We_top ; P2 = feat @ We_mid
        GArgs a{FA, 2048, 1024, W_e, W_e, BIG, P1h, 1024};
        GArgs b{FA, 2048, 1024, W_e + (size_t)D * D, W_e, BIG, P2h, 1024};
        gemm_h<<<dim3(8, 128, 2), blk, GM_SMEM>>>(a, b, D, nullptr, D, 0, 1);
    }
    {   // Q1 = w2v @ Wel_top ; Q2 = w2v @ Wel_bot
        GArgs a{WA, 608, 300, W_el, W_el, BIG, Q1h, 304};
        GArgs b{WA, 608, 300, W_el + (size_t)DL * DL, W_el, BIG, Q2h, 304};
        gemm_h<<<dim3(3, 128, 2), blk, GM_SMEM>>>(a, b, DL, nullptr, DL, 0, 1);
    }

    // ---- aggregation (gather, no atomics; SP reads sequential) ----
    agg_app_kernel<<<N_NODES, 256>>>(P1h, P2h, SPh, b_e, esrc, perm, rows, FA);
    agg_lang_kernel<<<N_NODES, 96>>>(Q1h, Q2h, b_el, esrc, perm, rows, WA);

    // ---- node updates ----
    {   // NF = relu([feat|AGG] @ W_nu + b_nu) -> NFA cols 0..1023
        GArgs a{FA, 2048, 2048, W_nu, W_nu, BIG, NFA, 1328};
        gemm_h<<<dim3(8, 128, 1), blk, GM_SMEM>>>(a, a, D, b_nu, D, 1, 1);
    }
    {   // NFL = relu([w2v|AGGL] @ W_nul + b_nul) -> NFA cols 1024..1323
        GArgs a{WA, 608, 600, W_nul, W_nul, BIG, NFA + 1024, 1328};
        gemm_h<<<dim3(3, 128, 1), blk, GM_SMEM>>>(a, a, DL, b_nul, DL, 1, 1);
    }

    // ---- predictor pre-projections (RD & RS merged; RS via two-segment B) ----
    {
        GArgs a{NFA, 1328, 1324, W_p, W_p, BIG, RD, NC};
        GArgs b{NFA, 1328, 1324,
                W_p + (size_t)(D + DL + DS + DL) * NC,   // NF part: rows 1640..2663
                W_p + (size_t)(D + DL + DS) * NC,        // NFL part: rows 1340..1639
                1024, RS, NC};
        gemm_h<<<dim3(1, 128, 2), blk, GM_SMEM>>>(a, b, NC, nullptr, NC, 0, 0);
    }

    // ---- final edge readout ----
    readout_kernel<<<NE_RO, 128>>>(RD, RS, SPRO, rsrc, rdst, pred);
}

// round 14
// speedup vs baseline: 1.1306x; 1.0329x over previous
#include <cuda_runtime.h>
#include <cuda_fp16.h>
#include <cstdint>
#include <cstddef>

// ---------------- problem dimensions ----------------
static constexpr int N_NODES = 16384;
static constexpr int NE      = 131072;
static constexpr int NE_RO   = 32768;
static constexpr int D       = 1024;
static constexpr int DL      = 300;
static constexpr int DS      = 16;
static constexpr int NC      = 117;

// ---------------- fp32 scratch (readout precursors) ----------------
static constexpr size_t SZ_NC   = (size_t)N_NODES * NC;
static constexpr size_t SZ_SPRO = (size_t)NE_RO * NC;
static constexpr size_t OFF_RD   = 0;
static constexpr size_t OFF_RS   = OFF_RD + SZ_NC;
static constexpr size_t OFF_SPRO = OFF_RS + SZ_NC;
static constexpr size_t TOTAL_F32 = OFF_SPRO + SZ_SPRO;
__device__ float g_scratch[TOTAL_F32];

// ---------------- fp16 scratch ----------------
static constexpr size_t HOFF_FA   = 0;                               // [N][2048] = [feat|AGG]
static constexpr size_t HSZ_FA    = (size_t)N_NODES * 2048;
static constexpr size_t HOFF_WA   = HOFF_FA + HSZ_FA;                // [N][608]  = [w2v|AGGL|pad]
static constexpr size_t HSZ_WA    = (size_t)N_NODES * 608;
static constexpr size_t HOFF_NFA  = HOFF_WA + HSZ_WA;                // [N][1328] = [NF|NFL|pad]
static constexpr size_t HSZ_NFA   = (size_t)N_NODES * 1328;
static constexpr size_t HOFF_P1   = HOFF_NFA + HSZ_NFA;
static constexpr size_t HSZ_P     = (size_t)N_NODES * 1024;
static constexpr size_t HOFF_P2   = HOFF_P1 + HSZ_P;
static constexpr size_t HOFF_Q1   = HOFF_P2 + HSZ_P;
static constexpr size_t HSZ_Q     = (size_t)N_NODES * 304;
static constexpr size_t HOFF_Q2   = HOFF_Q1 + HSZ_Q;
static constexpr size_t HOFF_SP   = HOFF_Q2 + HSZ_Q;
static constexpr size_t HSZ_SP    = (size_t)NE * 1024;
static constexpr size_t HOFF_SFH  = HOFF_SP + HSZ_SP;
static constexpr size_t HSZ_SFH   = (size_t)NE * 16;
static constexpr size_t HOFF_SFRO = HOFF_SFH + HSZ_SFH;
static constexpr size_t HSZ_SFRO  = (size_t)NE_RO * 16;
static constexpr size_t TOTAL_H   = HOFF_SFRO + HSZ_SFRO;
__device__ __half g_hscratch[TOTAL_H];

// int scratch
static constexpr size_t IOFF_DEG  = 0;
static constexpr size_t IOFF_RS_  = IOFF_DEG + N_NODES;
static constexpr size_t IOFF_CUR  = IOFF_RS_ + N_NODES + 1;
static constexpr size_t IOFF_PERM = IOFF_CUR + N_NODES;
__device__ int g_iscratch[IOFF_PERM + NE];

// ---------------- CSR build kernels ----------------
__global__ void zero_int_kernel(int* __restrict__ p, int n) {
    int i = blockIdx.x * blockDim.x + threadIdx.x;
    if (i < n) p[i] = 0;
}
__global__ void hist_kernel(const int* __restrict__ edst, int* __restrict__ deg) {
    int e = blockIdx.x * blockDim.x + threadIdx.x;
    if (e < NE) atomicAdd(&deg[edst[e]], 1);
}
__global__ __launch_bounds__(512)
void scan_kernel(const int* __restrict__ deg, int* __restrict__ row_start,
                 int* __restrict__ cursor) {
    __shared__ int part[512];
    int tid = threadIdx.x;
    int base = tid * 32;
    int loc[32];
    int s = 0;
#pragma unroll
    for (int j = 0; j < 32; j++) { loc[j] = s; s += deg[base + j]; }
    part[tid] = s;
    __syncthreads();
    for (int off = 1; off < 512; off <<= 1) {
        int v = (tid >= off) ? part[tid - off] : 0;
        __syncthreads();
        part[tid] += v;
        __syncthreads();
    }
    int pre = (tid > 0) ? part[tid - 1] : 0;
#pragma unroll
    for (int j = 0; j < 32; j++) {
        int v = pre + loc[j];
        row_start[base + j] = v;
        cursor[base + j] = v;
    }
    if (tid == 511) row_start[N_NODES] = part[511];
}
__global__ void scatter_kernel(const int* __restrict__ edst, int* __restrict__ cursor,
                               int* __restrict__ perm) {
    int e = blockIdx.x * blockDim.x + threadIdx.x;
    if (e < NE) {
        int pos = atomicAdd(&cursor[edst[e]], 1);
        perm[pos] = e;
    }
}

// ---------------- conversion kernels ----------------
__global__ __launch_bounds__(256)
void conv_node_kernel(const float* __restrict__ feat, const float* __restrict__ w2v,
                      __half* __restrict__ FA, __half* __restrict__ WA,
                      __half* __restrict__ NFA)
{
    int n = blockIdx.x, tid = threadIdx.x;
    float4 f = *(const float4*)(feat + (size_t)n * 1024 + tid * 4);
    __half2 h0 = __floats2half2_rn(f.x, f.y);
    __half2 h1 = __floats2half2_rn(f.z, f.w);
    uint2 u; u.x = *(uint32_t*)&h0; u.y = *(uint32_t*)&h1;
    *(uint2*)(FA + (size_t)n * 2048 + tid * 4) = u;
    if (tid < 75) {
        float4 w = *(const float4*)(w2v + (size_t)n * 300 + tid * 4);
        __half2 g0 = __floats2half2_rn(w.x, w.y);
        __half2 g1 = __floats2half2_rn(w.z, w.w);
        uint2 v; v.x = *(uint32_t*)&g0; v.y = *(uint32_t*)&g1;
        *(uint2*)(WA + (size_t)n * 608 + tid * 4) = v;
    } else if (tid == 75) {
        uint2 z = make_uint2(0, 0);
        *(uint2*)(WA + (size_t)n * 608 + 600) = z;
        *(uint2*)(WA + (size_t)n * 608 + 604) = z;
    } else if (tid == 76) {
        uint2 z = make_uint2(0, 0);
        *(uint2*)(NFA + (size_t)n * 1328 + 1324) = z;
    }
}

__global__ void conv_sf_kernel(const float* __restrict__ s_f, const float* __restrict__ s_f_ro,
                               __half* __restrict__ sfh, __half* __restrict__ sfroh)
{
    size_t i = (size_t)blockIdx.x * blockDim.x + threadIdx.x;   // pair index
    size_t n1 = (size_t)NE * 8;
    size_t tot = n1 + (size_t)NE_RO * 8;
    if (i >= tot) return;
    if (i < n1) {
        float2 f = *(const float2*)(s_f + i * 2);
        __half2 h = __floats2half2_rn(f.x, f.y);
        *(uint32_t*)(sfh + i * 2) = *(uint32_t*)&h;
    } else {
        size_t j = i - n1;
        float2 f = *(const float2*)(s_f_ro + j * 2);
        __half2 h = __floats2half2_rn(f.x, f.y);
        *(uint32_t*)(sfroh + j * 2) = *(uint32_t*)&h;
    }
}

// ---------------- fp16 pack + mma + cp.async helpers ----------------
__device__ __forceinline__ uint32_t f16_pack(float f0, float f1) {
    __half2 h = __floats2half2_rn(f0, f1);
    return *(uint32_t*)&h;
}
__device__ __forceinline__ void mma_f16(float* c, const uint32_t* a, const uint32_t* b) {
    asm volatile("mma.sync.aligned.m16n8k16.row.col.f32.f16.f16.f32 "
        "{%0,%1,%2,%3}, {%4,%5,%6,%7}, {%8,%9}, {%0,%1,%2,%3};"
        : "+f"(c[0]), "+f"(c[1]), "+f"(c[2]), "+f"(c[3])
        : "r"(a[0]), "r"(a[1]), "r"(a[2]), "r"(a[3]), "r"(b[0]), "r"(b[1]));
}
__device__ __forceinline__ uint32_t smem_u32(const void* p) {
    uint32_t a;
    asm("{ .reg .u64 t; cvta.to.shared.u64 t, %1; cvt.u32.u64 %0, t; }" : "=r"(a) : "l"(p));
    return a;
}
__device__ __forceinline__ void cp_async16(uint32_t dst, const void* src, int src_bytes) {
    asm volatile("cp.async.cg.shared.global [%0], [%1], 16, %2;"
                 :: "r"(dst), "l"(src), "r"(src_bytes) : "memory");
}
__device__ __forceinline__ void cp_async4(uint32_t dst, const void* src, int src_bytes) {
    asm volatile("cp.async.ca.shared.global [%0], [%1], 4, %2;"
                 :: "r"(dst), "l"(src), "r"(src_bytes) : "memory");
}
#define CP_COMMIT() asm volatile("cp.async.commit_group;" ::: "memory")
#define CP_WAIT(N)  asm volatile("cp.async.wait_group %0;" :: "n"(N) : "memory")

// ---------------- fp16-A GEMM, cp.async 3-stage pipeline, 2 CTAs/SM ----------------
struct GArgs {
    const __half* A; int lda; int K;
    const float* B1; const float* B2; int KB1;
    void* C; int ldc;
};

static constexpr int A_PAD_H   = 40;
static constexpr int A_BYTES   = 128 * A_PAD_H * 2;        // 10240
static constexpr int B_PAD     = 132;
static constexpr int B_BYTES   = 32 * B_PAD * 4;           // 16896
static constexpr int STG_BYTES = A_BYTES + B_BYTES;        // 27136
static constexpr int STAGES    = 3;
static constexpr int GM_SMEM   = STAGES * STG_BYTES;       // 81408

__global__ __launch_bounds__(256, 2)
void gemm_h(GArgs za, GArgs zb, int ldb, const float* __restrict__ bias,
            int Nn, int doRelu, int outHalf)
{
    extern __shared__ char smc[];
    GArgs ga = (blockIdx.z == 0) ? za : zb;

    const int tid  = threadIdx.x;
    const int wid  = tid >> 5;
    const int lane = tid & 31;
    const int g    = lane >> 2;
    const int t    = lane & 3;
    const int m0   = blockIdx.y * 128;
    const int n0   = blockIdx.x * 128;
    const int K    = ga.K;
    const int nT   = (K + 31) / 32;
    const int wm   = wid & 3;
    const int wn   = wid >> 2;
    const bool b_vec = ((ldb & 3) == 0);

    const uint32_t smb = smem_u32(smc);

    float acc[2][8][4];
#pragma unroll
    for (int i = 0; i < 2; i++)
#pragma unroll
        for (int j = 0; j < 8; j++)
#pragma unroll
            for (int k = 0; k < 4; k++) acc[i][j][k] = 0.f;

    auto issue_load = [&](int tt, int buf) {
        if (tt < nT) {
            const int k0 = tt * 32;
            uint32_t Ab = smb + (uint32_t)buf * STG_BYTES;
            uint32_t Bb_ = Ab + A_BYTES;
#pragma unroll
            for (int i = 0; i < 2; i++) {
                int idx = i * 256 + tid;
                int row = idx >> 2, c8 = idx & 3;
                int kb = k0 + c8 * 8;
                const __half* src = ga.A;
                int sz = 0;
                if (kb < K) { src = ga.A + (size_t)(m0 + row) * ga.lda + kb; sz = 16; }
                cp_async16(Ab + (uint32_t)(row * (A_PAD_H * 2) + c8 * 16), src, sz);
            }
            if (b_vec) {
#pragma unroll
                for (int i = 0; i < 4; i++) {
                    int idx = i * 256 + tid;
                    int k = idx >> 5, n4 = idx & 31;
                    int kg = k0 + k;
                    int nb4 = n0 + n4 * 4;
                    const float* src = ga.B1;
                    int sz = 0;
                    if (kg < K && nb4 + 3 < Nn) {
                        src = (kg < ga.KB1) ? (ga.B1 + (size_t)kg * ldb + nb4)
                                            : (ga.B2 + (size_t)(kg - ga.KB1) * ldb + nb4);
                        sz = 16;
                    }
                    cp_async16(Bb_ + (uint32_t)(k * B_PAD + n4 * 4) * 4, src, sz);
                }
            } else {
#pragma unroll
                for (int i = 0; i < 4; i++) {
                    int idx = i * 256 + tid;
                    int k = idx >> 5, n4 = idx & 31;
                    int kg = k0 + k;
#pragma unroll
                    for (int j = 0; j < 4; j++) {
                        int nn = n0 + n4 * 4 + j;
                        const float* src = ga.B1;
                        int sz = 0;
                        if (kg < K && nn < Nn) {
                            src = (kg < ga.KB1) ? (ga.B1 + (size_t)kg * ldb + nn)
                                                : (ga.B2 + (size_t)(kg - ga.KB1) * ldb + nn);
                            sz = 4;
                        }
                        cp_async4(Bb_ + (uint32_t)(k * B_PAD + n4 * 4 + j) * 4, src, sz);
                    }
                }
            }
        }
        CP_COMMIT();
    };

    auto compute = [&](int buf) {
        const __half* As = (const __half*)(smc + buf * STG_BYTES) + (wm * 32) * A_PAD_H;
        const float*  Bs = (const float*)(smc + buf * STG_BYTES + A_BYTES) + wn * 64;
#pragma unroll
        for (int ks = 0; ks < 2; ks++) {
            uint32_t ah[2][4];
#pragma unroll
            for (int mb = 0; mb < 2; mb++) {
#pragma unroll
                for (int r = 0; r < 4; r++) {
                    int rowq = mb * 16 + g + (r & 1) * 8;
                    int kq   = ks * 16 + t * 2 + (r >> 1) * 8;
                    ah[mb][r] = *(const uint32_t*)(As + rowq * A_PAD_H + kq);
                }
            }
            uint32_t bh[8][2];
#pragma unroll
            for (int nb = 0; nb < 8; nb++) {
#pragma unroll
                for (int r = 0; r < 2; r++) {
                    int kq = ks * 16 + t * 2 + r * 8;
                    float f0 = Bs[kq * B_PAD + nb * 8 + g];
                    float f1 = Bs[(kq + 1) * B_PAD + nb * 8 + g];
                    bh[nb][r] = f16_pack(f0, f1);
                }
            }
#pragma unroll
            for (int mb = 0; mb < 2; mb++) {
#pragma unroll
                for (int nb = 0; nb < 8; nb++) {
                    mma_f16(acc[mb][nb], ah[mb], bh[nb]);
                }
            }
        }
    };

#pragma unroll
    for (int s = 0; s < STAGES - 1; s++) issue_load(s, s);

    for (int tt = 0; tt < nT; tt++) {
        issue_load(tt + STAGES - 1, (tt + STAGES - 1) % STAGES);
        CP_WAIT(STAGES - 1);
        __syncthreads();
        compute(tt % STAGES);
        __syncthreads();
    }

    // ---- epilogue ----
#pragma unroll
    for (int mb = 0; mb < 2; mb++) {
#pragma unroll
        for (int nb = 0; nb < 8; nb++) {
            int n = n0 + wn * 64 + nb * 8 + t * 2;
            float bv0 = 0.f, bv1 = 0.f;
            if (bias) {
                if (n     < Nn) bv0 = bias[n];
                if (n + 1 < Nn) bv1 = bias[n + 1];
            }
#pragma unroll
            for (int h = 0; h < 2; h++) {
                int m = m0 + wm * 32 + mb * 16 + g + h * 8;
                float v0 = acc[mb][nb][h * 2 + 0] + bv0;
                float v1 = acc[mb][nb][h * 2 + 1] + bv1;
                if (doRelu) { v0 = fmaxf(v0, 0.f); v1 = fmaxf(v1, 0.f); }
                if (outHalf) {
                    if (n < Nn) {
                        __half2 hv = __floats2half2_rn(v0, v1);
                        *(uint32_t*)((__half*)ga.C + (size_t)m * ga.ldc + n) = *(uint32_t*)&hv;
                    }
                } else {
                    float* cp = (float*)ga.C + (size_t)m * ga.ldc + n;
                    if (n     < Nn) cp[0] = v0;
                    if (n + 1 < Nn) cp[1] = v1;
                }
            }
        }
    }
}

// ---------------- appearance aggregation (CSR gather, fp16 data) ----------------
__global__ __launch_bounds__(256)
void agg_app_kernel(const __half* __restrict__ P1h, const __half* __restrict__ P2h,
                    const __half* __restrict__ SPh, const float* __restrict__ b_e,
                    const int* __restrict__ esrc, const int* __restrict__ perm,
                    const int* __restrict__ row_start, __half* __restrict__ FA)
{
    const int n = blockIdx.x;
    const int tid = threadIdx.x;
    const int start = row_start[n];
    const int nb = row_start[n + 1] - start;

    uint2 p2 = *(const uint2*)(P2h + (size_t)n * 1024 + tid * 4);
    float2 b0 = __half22float2(*(__half2*)&p2.x);
    float2 b1 = __half22float2(*(__half2*)&p2.y);
    float4 be = ((const float4*)b_e)[tid];
    float bx = b0.x + be.x, by = b0.y + be.y, bz = b1.x + be.z, bw = b1.y + be.w;

    float4 acc = make_float4(0.f, 0.f, 0.f, 0.f);
#pragma unroll 2
    for (int i = 0; i < nb; i++) {
        int e = __ldg(&perm[start + i]);
        int s = __ldg(&esrc[e]);
        uint2 a = *(const uint2*)(P1h + (size_t)s * 1024 + tid * 4);
        uint2 c = *(const uint2*)(SPh + (size_t)e * 1024 + tid * 4);
        float2 a0 = __half22float2(*(__half2*)&a.x);
        float2 a1 = __half22float2(*(__half2*)&a.y);
        float2 c0 = __half22float2(*(__half2*)&c.x);
        float2 c1 = __half22float2(*(__half2*)&c.y);
        acc.x += fmaxf(a0.x + c0.x + bx, 0.f);
        acc.y += fmaxf(a0.y + c0.y + by, 0.f);
        acc.z += fmaxf(a1.x + c1.x + bz, 0.f);
        acc.w += fmaxf(a1.y + c1.y + bw, 0.f);
    }
    float inv = 1.0f / (float)max(nb, 1);
    __half2 o0 = __floats2half2_rn(acc.x * inv, acc.y * inv);
    __half2 o1 = __floats2half2_rn(acc.z * inv, acc.w * inv);
    uint2 o; o.x = *(uint32_t*)&o0; o.y = *(uint32_t*)&o1;
    *(uint2*)(FA + (size_t)n * 2048 + 1024 + tid * 4) = o;
}

// ---------------- language aggregation (CSR gather, fp16 data) ----------------
__global__ __launch_bounds__(96)
void agg_lang_kernel(const __half* __restrict__ Q1h, const __half* __restrict__ Q2h,
                     const float* __restrict__ b_el,
                     const int* __restrict__ esrc, const int* __restrict__ perm,
                     const int* __restrict__ row_start, __half* __restrict__ WA)
{
    const int n = blockIdx.x;
    const int c4 = threadIdx.x;
    if (c4 >= DL / 4) return;
    const int start = row_start[n];
    const int nb = row_start[n + 1] - start;

    uint2 q2 = *(const uint2*)(Q2h + (size_t)n * 304 + c4 * 4);
    float2 b0 = __half22float2(*(__half2*)&q2.x);
    float2 b1 = __half22float2(*(__half2*)&q2.y);
    float4 be = ((const float4*)b_el)[c4];
    float bx = b0.x + be.x, by = b0.y + be.y, bz = b1.x + be.z, bw = b1.y + be.w;

    float4 acc = make_float4(0.f, 0.f, 0.f, 0.f);
#pragma unroll 2
    for (int i = 0; i < nb; i++) {
        int e = __ldg(&perm[start + i]);
        int s = __ldg(&esrc[e]);
        uint2 a = *(const uint2*)(Q1h + (size_t)s * 304 + c4 * 4);
        float2 a0 = __half22float2(*(__half2*)&a.x);
        float2 a1 = __half22float2(*(__half2*)&a.y);
        acc.x += fmaxf(a0.x + bx, 0.f);
        acc.y += fmaxf(a0.y + by, 0.f);
        acc.z += fmaxf(a1.x + bz, 0.f);
        acc.w += fmaxf(a1.y + bw, 0.f);
    }
    float inv = 1.0f / (float)max(nb, 1);
    __half2 o0 = __floats2half2_rn(acc.x * inv, acc.y * inv);
    __half2 o1 = __floats2half2_rn(acc.z * inv, acc.w * inv);
    uint2 o; o.x = *(uint32_t*)&o0; o.y = *(uint32_t*)&o1;
    *(uint2*)(WA + (size_t)n * 608 + 300 + c4 * 4) = o;
}

// ---------------- readout ----------------
__global__ __launch_bounds__(128)
void readout_kernel(const float* __restrict__ Rd, const float* __restrict__ Rs,
                    const float* __restrict__ SPro,
                    const int* __restrict__ rsrc, const int* __restrict__ rdst,
                    float* __restrict__ pred)
{
    int e = blockIdx.x;
    int c = threadIdx.x;
    if (c >= NC) return;
    int s = rsrc[e];
    int d = rdst[e];
    pred[(size_t)e * NC + c] = Rd[(size_t)d * NC + c] + Rs[(size_t)s * NC + c]
                             + SPro[(size_t)e * NC + c];
}

// ---------------- host launcher ----------------
extern "C" void kernel_launch(void* const* d_in, const int* in_sizes, int n_in,
                              void* d_out, int out_size)
{
    const float* feat   = (const float*)d_in[0];
    const float* w2v    = (const float*)d_in[1];
    const float* s_f    = (const float*)d_in[2];
    const float* s_f_ro = (const float*)d_in[3];
    const float* W_e    = (const float*)d_in[4];
    const float* b_e    = (const float*)d_in[5];
    const float* W_el   = (const float*)d_in[6];
    const float* b_el   = (const float*)d_in[7];
    const float* W_nu   = (const float*)d_in[8];
    const float* b_nu   = (const float*)d_in[9];
    const float* W_nul  = (const float*)d_in[10];
    const float* b_nul  = (const float*)d_in[11];
    const float* W_p    = (const float*)d_in[12];
    const float* b_p    = (const float*)d_in[13];
    const int* esrc = (const int*)d_in[14];
    const int* edst = (const int*)d_in[15];
    const int* rsrc = (const int*)d_in[16];
    const int* rdst = (const int*)d_in[17];
    float* pred = (float*)d_out;

    float* sc = nullptr;
    cudaGetSymbolAddress((void**)&sc, g_scratch);
    __half* hs = nullptr;
    cudaGetSymbolAddress((void**)&hs, g_hscratch);
    int* isc = nullptr;
    cudaGetSymbolAddress((void**)&isc, g_iscratch);

    float* RD   = sc + OFF_RD;
    float* RS   = sc + OFF_RS;
    float* SPRO = sc + OFF_SPRO;

    __half* FA    = hs + HOFF_FA;
    __half* WA    = hs + HOFF_WA;
    __half* NFA   = hs + HOFF_NFA;
    __half* P1h   = hs + HOFF_P1;
    __half* P2h   = hs + HOFF_P2;
    __half* Q1h   = hs + HOFF_Q1;
    __half* Q2h   = hs + HOFF_Q2;
    __half* SPh   = hs + HOFF_SP;
    __half* sfh   = hs + HOFF_SFH;
    __half* sfroh = hs + HOFF_SFRO;

    int* deg  = isc + IOFF_DEG;
    int* rows = isc + IOFF_RS_;
    int* cur  = isc + IOFF_CUR;
    int* perm = isc + IOFF_PERM;

    cudaFuncSetAttribute(gemm_h, cudaFuncAttributeMaxDynamicSharedMemorySize, GM_SMEM);

    const float* Ws  = W_e + (size_t)(2 * D) * D;      // spatial rows of W_e, stride D
    const float* Wp3 = W_p + (size_t)(D + DL) * NC;    // spatial rows of W_p

    // ---- conversions ----
    conv_node_kernel<<<N_NODES, 256>>>(feat, w2v, FA, WA, NFA);
    {
        size_t pairs = ((size_t)NE + NE_RO) * 8;
        conv_sf_kernel<<<(unsigned)((pairs + 255) / 256), 256>>>(s_f, s_f_ro, sfh, sfroh);
    }

    // ---- CSR build (by dst) ----
    zero_int_kernel<<<(N_NODES + 255) / 256, 256>>>(deg, N_NODES);
    hist_kernel<<<NE / 256, 256>>>(edst, deg);
    scan_kernel<<<1, 512>>>(deg, rows, cur);
    scatter_kernel<<<NE / 256, 256>>>(edst, cur, perm);

    dim3 blk(256);
    const int BIG = 1 << 28;

    // ---- spatial pre-projections ----
    {   // SP[e] = s_f @ Ws  -> fp16 [NE,1024]
        GArgs a{sfh, 16, 16, Ws, Ws, BIG, SPh, 1024};
        gemm_h<<<dim3(8, NE / 128, 1), blk, GM_SMEM>>>(a, a, D, nullptr, D, 0, 1);
    }
    {   // SPro[e] = s_f_ro @ Wp3 + b_p -> fp32 [NE_RO,117]
        GArgs a{sfroh, 16, 16, Wp3, Wp3, BIG, SPRO, NC};
        gemm_h<<<dim3(1, 256, 1), blk, GM_SMEM>>>(a, a, NC, b_p, NC, 0, 0);
    }

    // ---- node-level pre-projections ----
    {   // P1 = feat @ We_top ; P2 = feat @ We_mid
        GArgs a{FA, 2048, 1024, W_e, W_e, BIG, P1h, 1024};
        GArgs b{FA, 2048, 1024, W_e + (size_t)D * D, W_e, BIG, P2h, 1024};
        gemm_h<<<dim3(8, 128, 2), blk, GM_SMEM>>>(a, b, D, nullptr, D, 0, 1);
    }
    {   // Q1 = w2v @ Wel_top ; Q2 = w2v @ Wel_bot
        GArgs a{WA, 608, 300, W_el, W_el, BIG, Q1h, 304};
        GArgs b{WA, 608, 300, W_el + (size_t)DL * DL, W_el, BIG, Q2h, 304};
        gemm_h<<<dim3(3, 128, 2), blk, GM_SMEM>>>(a, b, DL, nullptr, DL, 0, 1);
    }

    // ---- aggregation (gather, no atomics) ----
    agg_app_kernel<<<N_NODES, 256>>>(P1h, P2h, SPh, b_e, esrc, perm, rows, FA);
    agg_lang_kernel<<<N_NODES, 96>>>(Q1h, Q2h, b_el, esrc, perm, rows, WA);

    // ---- node updates ----
    {   // NF = relu([feat|AGG] @ W_nu + b_nu) -> NFA cols 0..1023
        GArgs a{FA, 2048, 2048, W_nu, W_nu, BIG, NFA, 1328};
        gemm_h<<<dim3(8, 128, 1), blk, GM_SMEM>>>(a, a, D, b_nu, D, 1, 1);
    }
    {   // NFL = relu([w2v|AGGL] @ W_nul + b_nul) -> NFA cols 1024..1323
        GArgs a{WA, 608, 600, W_nul, W_nul, BIG, NFA + 1024, 1328};
        gemm_h<<<dim3(3, 128, 1), blk, GM_SMEM>>>(a, a, DL, b_nul, DL, 1, 1);
    }

    // ---- predictor pre-projections (RD & RS merged; RS via two-segment B) ----
    {
        GArgs a{NFA, 1328, 1324, W_p, W_p, BIG, RD, NC};
        GArgs b{NFA, 1328, 1324,
                W_p + (size_t)(D + DL + DS + DL) * NC,   // NF part: rows 1640..2663
                W_p + (size_t)(D + DL + DS) * NC,        // NFL part: rows 1340..1639
                1024, RS, NC};
        gemm_h<<<dim3(1, 128, 2), blk, GM_SMEM>>>(a, b, NC, nullptr, NC, 0, 0);
    }

    // ---- final edge readout ----
    readout_kernel<<<NE_RO, 128>>>(RD, RS, SPRO, rsrc, rdst, pred);
}